// round 1
// baseline (speedup 1.0000x reference)
#include <cuda_runtime.h>
#include <math.h>

// Problem constants
#define Bdim 2
#define Nseq 2048
#define Dmod 1024
#define Hn   16
#define HD   64

// Scratch (alloc-free rule: __device__ globals)
__device__ float g_Q[(size_t)Bdim * Hn * Nseq * HD];   // [b][h][n][d]
__device__ float g_K[(size_t)Bdim * Hn * Nseq * HD];   // [b][h][n][d]
__device__ float g_V[(size_t)Bdim * Hn * Nseq * HD];   // [b][h][n][d]
__device__ float g_O[(size_t)Bdim * Nseq * Dmod];      // [b][n][h*HD+d]

// ---------------------------------------------------------------------------
// SGEMM body: C[M=4096, 1024] = A[4096,1024] @ W[1024,1024] + bias
// 128x128 tile, BK=16, 256 threads, 8x8 per thread (split 4+4 pattern).
// HEAD=true scatters output into [b][h][n][d] layout.
// ---------------------------------------------------------------------------
template <bool HEAD>
__device__ __forceinline__ void gemm_body(const float* __restrict__ A,
                                          const float* __restrict__ W,
                                          const float* __restrict__ bias,
                                          float* __restrict__ out)
{
    __shared__ float As[16][128];   // [k][m] (transposed)
    __shared__ float Ws[16][128];   // [k][n]

    const int tid = threadIdx.x;
    const int tx = tid & 15;
    const int ty = tid >> 4;
    const int m0 = blockIdx.y * 128;
    const int n0 = blockIdx.x * 128;

    float acc[8][8];
#pragma unroll
    for (int i = 0; i < 8; i++)
#pragma unroll
        for (int j = 0; j < 8; j++) acc[i][j] = 0.f;

    for (int kt = 0; kt < 1024; kt += 16) {
        // Load A tile (128x16) -> transposed smem
#pragma unroll
        for (int q = 0; q < 2; q++) {
            int f = tid * 2 + q;            // 0..511 float4s
            int row = f >> 2;               // 128 rows, 4 float4/row
            int c4 = f & 3;
            float4 v = *(const float4*)(A + (size_t)(m0 + row) * 1024 + kt + c4 * 4);
            As[c4 * 4 + 0][row] = v.x;
            As[c4 * 4 + 1][row] = v.y;
            As[c4 * 4 + 2][row] = v.z;
            As[c4 * 4 + 3][row] = v.w;
        }
        // Load W tile (16x128)
#pragma unroll
        for (int q = 0; q < 2; q++) {
            int f = tid * 2 + q;
            int row = f >> 5;               // 16 rows, 32 float4/row
            int c4 = f & 31;
            *(float4*)&Ws[row][c4 * 4] =
                *(const float4*)(W + (size_t)(kt + row) * 1024 + n0 + c4 * 4);
        }
        __syncthreads();

#pragma unroll
        for (int kk = 0; kk < 16; kk++) {
            float4 a0 = *(const float4*)&As[kk][ty * 4];
            float4 a1 = *(const float4*)&As[kk][64 + ty * 4];
            float4 b0 = *(const float4*)&Ws[kk][tx * 4];
            float4 b1 = *(const float4*)&Ws[kk][64 + tx * 4];
            float ar[8] = {a0.x, a0.y, a0.z, a0.w, a1.x, a1.y, a1.z, a1.w};
            float bc[8] = {b0.x, b0.y, b0.z, b0.w, b1.x, b1.y, b1.z, b1.w};
#pragma unroll
            for (int i = 0; i < 8; i++)
#pragma unroll
                for (int j = 0; j < 8; j++) acc[i][j] += ar[i] * bc[j];
        }
        __syncthreads();
    }

    // Epilogue
#pragma unroll
    for (int i = 0; i < 8; i++) {
        int r = (i < 4) ? (ty * 4 + i) : (64 + ty * 4 + (i - 4));
        int m = m0 + r;
        int b = m >> 11;           // /2048
        int n = m & 2047;
#pragma unroll
        for (int j = 0; j < 8; j++) {
            int c = (j < 4) ? (tx * 4 + j) : (64 + tx * 4 + (j - 4));
            int col = n0 + c;
            float val = acc[i][j] + bias[col];
            if (HEAD) {
                int h = col >> 6;  // /64
                int d = col & 63;
                out[(((size_t)(b * Hn + h)) * Nseq + n) * HD + d] = val;
            } else {
                out[(size_t)m * 1024 + col] = val;
            }
        }
    }
}

__global__ void __launch_bounds__(256, 2)
qkv_gemm(const float* __restrict__ x,
         const float* __restrict__ Wq, const float* __restrict__ bq,
         const float* __restrict__ Wk, const float* __restrict__ bk,
         const float* __restrict__ Wv, const float* __restrict__ bv)
{
    const float* W;
    const float* bias;
    float* out;
    if (blockIdx.z == 0)      { W = Wq; bias = bq; out = g_Q; }
    else if (blockIdx.z == 1) { W = Wk; bias = bk; out = g_K; }
    else                      { W = Wv; bias = bv; out = g_V; }
    gemm_body<true>(x, W, bias, out);
}

__global__ void __launch_bounds__(256, 2)
out_gemm(const float* __restrict__ Wo, const float* __restrict__ bo,
         float* __restrict__ out)
{
    gemm_body<false>(g_O, Wo, bo, out);
}

// ---------------------------------------------------------------------------
// Flash attention per (b, h): BQ=64 queries per CTA, loop over 32 key blocks
// of 64. Online softmax. Bias = lam * B_gaussian[b] loaded directly from gmem.
// 256 threads: 16x16 grid, 4x4 microtile of S / O per thread.
// Smem: Qs(16K) + KPs(16K, K tile aliased with P tile) + Vs(16K) = 48 KB.
// ---------------------------------------------------------------------------
__global__ void __launch_bounds__(256)
attn_kernel(const float* __restrict__ Bg, const float* __restrict__ lam_p)
{
    __shared__ float Qs[64][64];    // [d][r]
    __shared__ float KPs[64][64];   // phase 1: K as [d][c]; phase 2: P as [r][j]
    __shared__ float Vs[64][64];    // [j][d]

    const int tid = threadIdx.x;
    const int tx = tid & 15;
    const int ty = tid >> 4;
    const int qb = blockIdx.x;
    const int h  = blockIdx.y;
    const int b  = blockIdx.z;

    const float lam = __ldg(lam_p);
    const float scale = 0.125f;     // 1/sqrt(64)

    const float* Qg = g_Q + (((size_t)(b * Hn + h)) * Nseq + qb * 64) * HD;
    // Load Q tile transposed: [d][r]
#pragma unroll
    for (int q = 0; q < 4; q++) {
        int f = tid + q * 256;      // 0..1023 float4s
        int r = f >> 4;
        int d4 = f & 15;
        float4 v = *(const float4*)(Qg + r * 64 + d4 * 4);
        Qs[d4 * 4 + 0][r] = v.x;
        Qs[d4 * 4 + 1][r] = v.y;
        Qs[d4 * 4 + 2][r] = v.z;
        Qs[d4 * 4 + 3][r] = v.w;
    }

    float m_i[4], l_i[4], oacc[4][4];
#pragma unroll
    for (int i = 0; i < 4; i++) {
        m_i[i] = -1e30f;
        l_i[i] = 0.f;
#pragma unroll
        for (int j = 0; j < 4; j++) oacc[i][j] = 0.f;
    }

    const float* Bgb = Bg + (size_t)b * Nseq * Nseq;
    const int qrow0 = qb * 64 + ty * 4;

    __syncthreads();

    for (int kb = 0; kb < 32; kb++) {
        const float* Kg = g_K + (((size_t)(b * Hn + h)) * Nseq + kb * 64) * HD;
        const float* Vg = g_V + (((size_t)(b * Hn + h)) * Nseq + kb * 64) * HD;
#pragma unroll
        for (int q = 0; q < 4; q++) {
            int f = tid + q * 256;
            int r = f >> 4;
            int d4 = f & 15;
            float4 kv = *(const float4*)(Kg + r * 64 + d4 * 4);
            KPs[d4 * 4 + 0][r] = kv.x;
            KPs[d4 * 4 + 1][r] = kv.y;
            KPs[d4 * 4 + 2][r] = kv.z;
            KPs[d4 * 4 + 3][r] = kv.w;
            *(float4*)&Vs[r][d4 * 4] = *(const float4*)(Vg + r * 64 + d4 * 4);
        }
        __syncthreads();

        // S = Q @ K^T, 4x4 microtile per thread
        float s[4][4];
#pragma unroll
        for (int i = 0; i < 4; i++)
#pragma unroll
            for (int j = 0; j < 4; j++) s[i][j] = 0.f;

#pragma unroll 16
        for (int d = 0; d < 64; d++) {
            float4 a = *(const float4*)&Qs[d][ty * 4];
            float4 k = *(const float4*)&KPs[d][tx * 4];
            float ar[4] = {a.x, a.y, a.z, a.w};
            float kc[4] = {k.x, k.y, k.z, k.w};
#pragma unroll
            for (int i = 0; i < 4; i++)
#pragma unroll
                for (int j = 0; j < 4; j++) s[i][j] += ar[i] * kc[j];
        }

        // Scale + Gaussian bias
        const int kc0 = kb * 64 + tx * 4;
#pragma unroll
        for (int i = 0; i < 4; i++) {
            float4 bg = *(const float4*)(Bgb + (size_t)(qrow0 + i) * Nseq + kc0);
            s[i][0] = s[i][0] * scale + lam * bg.x;
            s[i][1] = s[i][1] * scale + lam * bg.y;
            s[i][2] = s[i][2] * scale + lam * bg.z;
            s[i][3] = s[i][3] * scale + lam * bg.w;
        }

        // Online softmax (row groups of 16 lanes share a row)
#pragma unroll
        for (int i = 0; i < 4; i++) {
            float mx = fmaxf(fmaxf(s[i][0], s[i][1]), fmaxf(s[i][2], s[i][3]));
#pragma unroll
            for (int o = 8; o >= 1; o >>= 1)
                mx = fmaxf(mx, __shfl_xor_sync(0xffffffffu, mx, o, 16));
            float mn = fmaxf(m_i[i], mx);
            float corr = __expf(m_i[i] - mn);
            m_i[i] = mn;
            float rs = 0.f;
#pragma unroll
            for (int j = 0; j < 4; j++) {
                s[i][j] = __expf(s[i][j] - mn);
                rs += s[i][j];
            }
#pragma unroll
            for (int o = 8; o >= 1; o >>= 1)
                rs += __shfl_xor_sync(0xffffffffu, rs, o, 16);
            l_i[i] = l_i[i] * corr + rs;
#pragma unroll
            for (int j = 0; j < 4; j++) oacc[i][j] *= corr;
        }

        // P tile reuses K tile storage — wait for all S reads to finish
        __syncthreads();
#pragma unroll
        for (int i = 0; i < 4; i++)
            *(float4*)&KPs[ty * 4 + i][tx * 4] =
                make_float4(s[i][0], s[i][1], s[i][2], s[i][3]);
        __syncthreads();

        // O += P @ V
#pragma unroll 4
        for (int j4 = 0; j4 < 16; j4++) {
            float4 p0 = *(const float4*)&KPs[ty * 4 + 0][j4 * 4];
            float4 p1 = *(const float4*)&KPs[ty * 4 + 1][j4 * 4];
            float4 p2 = *(const float4*)&KPs[ty * 4 + 2][j4 * 4];
            float4 p3 = *(const float4*)&KPs[ty * 4 + 3][j4 * 4];
            float4 v0 = *(const float4*)&Vs[j4 * 4 + 0][tx * 4];
            float4 v1 = *(const float4*)&Vs[j4 * 4 + 1][tx * 4];
            float4 v2 = *(const float4*)&Vs[j4 * 4 + 2][tx * 4];
            float4 v3 = *(const float4*)&Vs[j4 * 4 + 3][tx * 4];

            oacc[0][0] += p0.x * v0.x + p0.y * v1.x + p0.z * v2.x + p0.w * v3.x;
            oacc[0][1] += p0.x * v0.y + p0.y * v1.y + p0.z * v2.y + p0.w * v3.y;
            oacc[0][2] += p0.x * v0.z + p0.y * v1.z + p0.z * v2.z + p0.w * v3.z;
            oacc[0][3] += p0.x * v0.w + p0.y * v1.w + p0.z * v2.w + p0.w * v3.w;

            oacc[1][0] += p1.x * v0.x + p1.y * v1.x + p1.z * v2.x + p1.w * v3.x;
            oacc[1][1] += p1.x * v0.y + p1.y * v1.y + p1.z * v2.y + p1.w * v3.y;
            oacc[1][2] += p1.x * v0.z + p1.y * v1.z + p1.z * v2.z + p1.w * v3.z;
            oacc[1][3] += p1.x * v0.w + p1.y * v1.w + p1.z * v2.w + p1.w * v3.w;

            oacc[2][0] += p2.x * v0.x + p2.y * v1.x + p2.z * v2.x + p2.w * v3.x;
            oacc[2][1] += p2.x * v0.y + p2.y * v1.y + p2.z * v2.y + p2.w * v3.y;
            oacc[2][2] += p2.x * v0.z + p2.y * v1.z + p2.z * v2.z + p2.w * v3.z;
            oacc[2][3] += p2.x * v0.w + p2.y * v1.w + p2.z * v2.w + p2.w * v3.w;

            oacc[3][0] += p3.x * v0.x + p3.y * v1.x + p3.z * v2.x + p3.w * v3.x;
            oacc[3][1] += p3.x * v0.y + p3.y * v1.y + p3.z * v2.y + p3.w * v3.y;
            oacc[3][2] += p3.x * v0.z + p3.y * v1.z + p3.z * v2.z + p3.w * v3.z;
            oacc[3][3] += p3.x * v0.w + p3.y * v1.w + p3.z * v2.w + p3.w * v3.w;
        }
        __syncthreads();
    }

    // Epilogue: normalize and write O in [b][n][h*HD+d] layout
    float* Og = g_O + ((size_t)(b * Nseq) + qb * 64 + ty * 4) * Dmod + h * HD + tx * 4;
#pragma unroll
    for (int i = 0; i < 4; i++) {
        float inv = 1.0f / l_i[i];
        *(float4*)(Og + (size_t)i * Dmod) =
            make_float4(oacc[i][0] * inv, oacc[i][1] * inv,
                        oacc[i][2] * inv, oacc[i][3] * inv);
    }
}

// ---------------------------------------------------------------------------
extern "C" void kernel_launch(void* const* d_in, const int* in_sizes, int n_in,
                              void* d_out, int out_size)
{
    const float* x   = (const float*)d_in[0];
    const float* Bg  = (const float*)d_in[1];
    const float* Wq  = (const float*)d_in[2];
    const float* bq  = (const float*)d_in[3];
    const float* Wk  = (const float*)d_in[4];
    const float* bk  = (const float*)d_in[5];
    const float* Wv  = (const float*)d_in[6];
    const float* bv  = (const float*)d_in[7];
    const float* Wo  = (const float*)d_in[8];
    const float* bo  = (const float*)d_in[9];
    const float* lam = (const float*)d_in[10];
    float* out = (float*)d_out;

    dim3 blk(256);
    qkv_gemm<<<dim3(8, 32, 3), blk>>>(x, Wq, bq, Wk, bk, Wv, bv);
    attn_kernel<<<dim3(32, 16, 2), blk>>>(Bg, lam);
    out_gemm<<<dim3(8, 32, 1), blk>>>(Wo, bo, out);
}

// round 3
// speedup vs baseline: 1.2945x; 1.2945x over previous
#include <cuda_runtime.h>
#include <cuda_bf16.h>
#include <cstdint>
#include <math.h>

// Problem constants
#define Bdim 2
#define Nseq 2048
#define Dmod 1024
#define Hn   16
#define HD   64

// ---------------------------------------------------------------------------
// Scratch (alloc-free rule: __device__ globals)
// ---------------------------------------------------------------------------
__device__ float g_Q[(size_t)Bdim * Hn * Nseq * HD];   // [b][h][n][d]
__device__ float g_K[(size_t)Bdim * Hn * Nseq * HD];
__device__ float g_V[(size_t)Bdim * Hn * Nseq * HD];
__device__ float g_O[(size_t)Bdim * Nseq * Dmod];      // [b][n][h*HD+d]

// bf16 hi/lo split operands
__device__ __nv_bfloat16 g_xh[(size_t)4096 * 1024];
__device__ __nv_bfloat16 g_xl[(size_t)4096 * 1024];
__device__ __nv_bfloat16 g_oh[(size_t)4096 * 1024];
__device__ __nv_bfloat16 g_ol[(size_t)4096 * 1024];
__device__ __nv_bfloat16 g_wth[4][(size_t)1024 * 1024];  // W^T [n][k]
__device__ __nv_bfloat16 g_wtl[4][(size_t)1024 * 1024];

// ---------------------------------------------------------------------------
// HMMA: m16n8k16 bf16 x bf16 -> f32 (baseline PTX, works on compute_103)
// A row-major, B col-major (we store B as [n][k], which IS col-major k x n).
// ---------------------------------------------------------------------------
__device__ __forceinline__ void mma_bf16(float (&d)[4],
                                         const uint32_t (&a)[4],
                                         const uint32_t (&b)[2])
{
    asm volatile(
        "mma.sync.aligned.m16n8k16.row.col.f32.bf16.bf16.f32 "
        "{%0,%1,%2,%3}, {%4,%5,%6,%7}, {%8,%9}, {%0,%1,%2,%3};"
        : "+f"(d[0]), "+f"(d[1]), "+f"(d[2]), "+f"(d[3])
        : "r"(a[0]), "r"(a[1]), "r"(a[2]), "r"(a[3]),
          "r"(b[0]), "r"(b[1]));
}

// ---------------------------------------------------------------------------
// Conversion kernels: fp32 -> (bf16 hi, bf16 lo)
// ---------------------------------------------------------------------------
__device__ __forceinline__ void split4(float4 v, ushort4& H, ushort4& L)
{
    __nv_bfloat16 h0 = __float2bfloat16_rn(v.x);
    __nv_bfloat16 h1 = __float2bfloat16_rn(v.y);
    __nv_bfloat16 h2 = __float2bfloat16_rn(v.z);
    __nv_bfloat16 h3 = __float2bfloat16_rn(v.w);
    H = {__bfloat16_as_ushort(h0), __bfloat16_as_ushort(h1),
         __bfloat16_as_ushort(h2), __bfloat16_as_ushort(h3)};
    L = {__bfloat16_as_ushort(__float2bfloat16_rn(v.x - __bfloat162float(h0))),
         __bfloat16_as_ushort(__float2bfloat16_rn(v.y - __bfloat162float(h1))),
         __bfloat16_as_ushort(__float2bfloat16_rn(v.z - __bfloat162float(h2))),
         __bfloat16_as_ushort(__float2bfloat16_rn(v.w - __bfloat162float(h3)))};
}

__global__ void conv_split_x(const float4* __restrict__ src)
{
    int i = blockIdx.x * 256 + threadIdx.x;
    ushort4 H, L;
    split4(src[i], H, L);
    ((ushort4*)g_xh)[i] = H;
    ((ushort4*)g_xl)[i] = L;
}

__global__ void conv_split_o()
{
    int i = blockIdx.x * 256 + threadIdx.x;
    ushort4 H, L;
    split4(((const float4*)g_O)[i], H, L);
    ((ushort4*)g_oh)[i] = H;
    ((ushort4*)g_ol)[i] = L;
}

// W [k][n] row-major -> W^T [n][k] hi/lo bf16
__global__ void conv_w(const float* __restrict__ Wq, const float* __restrict__ Wk,
                       const float* __restrict__ Wv, const float* __restrict__ Wo)
{
    __shared__ float t[32][33];
    int z = blockIdx.z;
    const float* W = (z == 0) ? Wq : (z == 1) ? Wk : (z == 2) ? Wv : Wo;
    int n0 = blockIdx.x * 32, k0 = blockIdx.y * 32;
    int tx = threadIdx.x, ty = threadIdx.y;
#pragma unroll
    for (int j = 0; j < 32; j += 8)
        t[ty + j][tx] = W[(size_t)(k0 + ty + j) * 1024 + n0 + tx];
    __syncthreads();
#pragma unroll
    for (int j = 0; j < 32; j += 8) {
        float v = t[tx][ty + j];
        __nv_bfloat16 h = __float2bfloat16_rn(v);
        __nv_bfloat16 l = __float2bfloat16_rn(v - __bfloat162float(h));
        size_t idx = (size_t)(n0 + ty + j) * 1024 + k0 + tx;
        g_wth[z][idx] = h;
        g_wtl[z][idx] = l;
    }
}

// ---------------------------------------------------------------------------
// HMMA bf16x3 GEMM: C[4096,1024] = A @ B^T + bias   (B stored as [n][k])
// CTA tile 128x128, K-chunk 32. 8 warps: 4(m) x 2(n); warp tile 32x64.
// Smem: 4 tiles of 128 rows x 32 bf16, row stride 20 b32 (80B) -> 40KB.
// Per-lane fragment loads are bank-conflict-free (banks (20r+c) mod 32).
// ---------------------------------------------------------------------------
#define TSTRIDE 20

template <bool HEAD>
__device__ __forceinline__ void mma_gemm_body(const __nv_bfloat16* __restrict__ Ahi,
                                              const __nv_bfloat16* __restrict__ Alo,
                                              const __nv_bfloat16* __restrict__ Bhi,
                                              const __nv_bfloat16* __restrict__ Blo,
                                              const float* __restrict__ bias,
                                              float* __restrict__ out)
{
    __shared__ uint32_t Ah[128 * TSTRIDE];
    __shared__ uint32_t Al[128 * TSTRIDE];
    __shared__ uint32_t Bh[128 * TSTRIDE];
    __shared__ uint32_t Bl[128 * TSTRIDE];

    const int tid = threadIdx.x;
    const int wid = tid >> 5;
    const int lid = tid & 31;
    const int wm  = wid & 3;        // warp row: 32 m-rows each
    const int wn  = wid >> 2;       // warp col: 64 n-cols each
    const int gq  = lid >> 2;       // group id 0..7
    const int tq  = lid & 3;        // thread in group
    const int m0 = blockIdx.y * 128;
    const int n0 = blockIdx.x * 128;

    float acc[2][8][4];
#pragma unroll
    for (int mt = 0; mt < 2; mt++)
#pragma unroll
        for (int nt = 0; nt < 8; nt++)
#pragma unroll
            for (int e = 0; e < 4; e++) acc[mt][nt][e] = 0.f;

    for (int kt = 0; kt < 1024; kt += 32) {
        // Load 4 tiles: 128 rows x 32 bf16 (= 4 uint4 per row)
#pragma unroll
        for (int q = 0; q < 2; q++) {
            int u = tid * 2 + q;        // 0..511
            int row = u >> 2;
            int c4 = u & 3;
            size_t ga = (size_t)(m0 + row) * 1024 + kt;
            size_t gb = (size_t)(n0 + row) * 1024 + kt;
            *(uint4*)&Ah[row * TSTRIDE + c4 * 4] = ((const uint4*)(Ahi + ga))[c4];
            *(uint4*)&Al[row * TSTRIDE + c4 * 4] = ((const uint4*)(Alo + ga))[c4];
            *(uint4*)&Bh[row * TSTRIDE + c4 * 4] = ((const uint4*)(Bhi + gb))[c4];
            *(uint4*)&Bl[row * TSTRIDE + c4 * 4] = ((const uint4*)(Blo + gb))[c4];
        }
        __syncthreads();

#pragma unroll
        for (int ks = 0; ks < 2; ks++) {
            const int c0 = ks * 8;
            // B fragments for 8 n-tiles (hi & lo)
            uint32_t bh[8][2], bl[8][2];
#pragma unroll
            for (int nt = 0; nt < 8; nt++) {
                int brow = (wn * 64 + nt * 8 + gq) * TSTRIDE + c0 + tq;
                bh[nt][0] = Bh[brow];
                bh[nt][1] = Bh[brow + 4];
                bl[nt][0] = Bl[brow];
                bl[nt][1] = Bl[brow + 4];
            }
#pragma unroll
            for (int mt = 0; mt < 2; mt++) {
                int ar0 = (wm * 32 + mt * 16 + gq) * TSTRIDE + c0 + tq;
                int ar1 = ar0 + 8 * TSTRIDE;
                uint32_t ah[4], al[4];
                ah[0] = Ah[ar0];     ah[1] = Ah[ar1];
                ah[2] = Ah[ar0 + 4]; ah[3] = Ah[ar1 + 4];
                al[0] = Al[ar0];     al[1] = Al[ar1];
                al[2] = Al[ar0 + 4]; al[3] = Al[ar1 + 4];
#pragma unroll
                for (int nt = 0; nt < 8; nt++) {
                    mma_bf16(acc[mt][nt], ah, bh[nt]);
                    mma_bf16(acc[mt][nt], ah, bl[nt]);
                    mma_bf16(acc[mt][nt], al, bh[nt]);
                }
            }
        }
        __syncthreads();
    }

    // Epilogue: acc layout: c0,c1 -> (row gq, cols 2tq, 2tq+1); c2,c3 -> row gq+8
#pragma unroll
    for (int mt = 0; mt < 2; mt++) {
#pragma unroll
        for (int nt = 0; nt < 8; nt++) {
            int R = m0 + wm * 32 + mt * 16 + gq;
            int C = n0 + wn * 64 + nt * 8 + tq * 2;
            float b0 = bias[C], b1 = bias[C + 1];
#pragma unroll
            for (int half = 0; half < 2; half++) {
                int r = R + half * 8;
                float v0 = acc[mt][nt][half * 2 + 0] + b0;
                float v1 = acc[mt][nt][half * 2 + 1] + b1;
                if (HEAD) {
                    int b = r >> 11;
                    int n = r & 2047;
                    int h = C >> 6;
                    int d = C & 63;
                    float2* dst = (float2*)(out +
                        (((size_t)(b * Hn + h)) * Nseq + n) * HD + d);
                    *dst = make_float2(v0, v1);
                } else {
                    *(float2*)(out + (size_t)r * 1024 + C) = make_float2(v0, v1);
                }
            }
        }
    }
}

__global__ void __launch_bounds__(256, 2)
mma_qkv(const float* __restrict__ bq, const float* __restrict__ bk,
        const float* __restrict__ bv)
{
    int z = blockIdx.z;
    const float* bias = (z == 0) ? bq : (z == 1) ? bk : bv;
    float* out = (z == 0) ? g_Q : (z == 1) ? g_K : g_V;
    mma_gemm_body<true>(g_xh, g_xl, g_wth[z], g_wtl[z], bias, out);
}

__global__ void __launch_bounds__(256, 2)
mma_out(const float* __restrict__ bo, float* __restrict__ out)
{
    mma_gemm_body<false>(g_oh, g_ol, g_wth[3], g_wtl[3], bo, out);
}

// ---------------------------------------------------------------------------
// Flash attention (unchanged FFMA version from R1)
// ---------------------------------------------------------------------------
__global__ void __launch_bounds__(256)
attn_kernel(const float* __restrict__ Bg, const float* __restrict__ lam_p)
{
    __shared__ float Qs[64][64];
    __shared__ float KPs[64][64];
    __shared__ float Vs[64][64];

    const int tid = threadIdx.x;
    const int tx = tid & 15;
    const int ty = tid >> 4;
    const int qb = blockIdx.x;
    const int h  = blockIdx.y;
    const int b  = blockIdx.z;

    const float lam = __ldg(lam_p);
    const float scale = 0.125f;

    const float* Qg = g_Q + (((size_t)(b * Hn + h)) * Nseq + qb * 64) * HD;
#pragma unroll
    for (int q = 0; q < 4; q++) {
        int f = tid + q * 256;
        int r = f >> 4;
        int d4 = f & 15;
        float4 v = *(const float4*)(Qg + r * 64 + d4 * 4);
        Qs[d4 * 4 + 0][r] = v.x;
        Qs[d4 * 4 + 1][r] = v.y;
        Qs[d4 * 4 + 2][r] = v.z;
        Qs[d4 * 4 + 3][r] = v.w;
    }

    float m_i[4], l_i[4], oacc[4][4];
#pragma unroll
    for (int i = 0; i < 4; i++) {
        m_i[i] = -1e30f;
        l_i[i] = 0.f;
#pragma unroll
        for (int j = 0; j < 4; j++) oacc[i][j] = 0.f;
    }

    const float* Bgb = Bg + (size_t)b * Nseq * Nseq;
    const int qrow0 = qb * 64 + ty * 4;

    __syncthreads();

    for (int kb = 0; kb < 32; kb++) {
        const float* Kg = g_K + (((size_t)(b * Hn + h)) * Nseq + kb * 64) * HD;
        const float* Vg = g_V + (((size_t)(b * Hn + h)) * Nseq + kb * 64) * HD;
#pragma unroll
        for (int q = 0; q < 4; q++) {
            int f = tid + q * 256;
            int r = f >> 4;
            int d4 = f & 15;
            float4 kv = *(const float4*)(Kg + r * 64 + d4 * 4);
            KPs[d4 * 4 + 0][r] = kv.x;
            KPs[d4 * 4 + 1][r] = kv.y;
            KPs[d4 * 4 + 2][r] = kv.z;
            KPs[d4 * 4 + 3][r] = kv.w;
            *(float4*)&Vs[r][d4 * 4] = *(const float4*)(Vg + r * 64 + d4 * 4);
        }
        __syncthreads();

        float s[4][4];
#pragma unroll
        for (int i = 0; i < 4; i++)
#pragma unroll
            for (int j = 0; j < 4; j++) s[i][j] = 0.f;

#pragma unroll 16
        for (int d = 0; d < 64; d++) {
            float4 a = *(const float4*)&Qs[d][ty * 4];
            float4 k = *(const float4*)&KPs[d][tx * 4];
            float ar[4] = {a.x, a.y, a.z, a.w};
            float kc[4] = {k.x, k.y, k.z, k.w};
#pragma unroll
            for (int i = 0; i < 4; i++)
#pragma unroll
                for (int j = 0; j < 4; j++) s[i][j] += ar[i] * kc[j];
        }

        const int kc0 = kb * 64 + tx * 4;
#pragma unroll
        for (int i = 0; i < 4; i++) {
            float4 bg = *(const float4*)(Bgb + (size_t)(qrow0 + i) * Nseq + kc0);
            s[i][0] = s[i][0] * scale + lam * bg.x;
            s[i][1] = s[i][1] * scale + lam * bg.y;
            s[i][2] = s[i][2] * scale + lam * bg.z;
            s[i][3] = s[i][3] * scale + lam * bg.w;
        }

#pragma unroll
        for (int i = 0; i < 4; i++) {
            float mx = fmaxf(fmaxf(s[i][0], s[i][1]), fmaxf(s[i][2], s[i][3]));
#pragma unroll
            for (int o = 8; o >= 1; o >>= 1)
                mx = fmaxf(mx, __shfl_xor_sync(0xffffffffu, mx, o, 16));
            float mn = fmaxf(m_i[i], mx);
            float corr = __expf(m_i[i] - mn);
            m_i[i] = mn;
            float rs = 0.f;
#pragma unroll
            for (int j = 0; j < 4; j++) {
                s[i][j] = __expf(s[i][j] - mn);
                rs += s[i][j];
            }
#pragma unroll
            for (int o = 8; o >= 1; o >>= 1)
                rs += __shfl_xor_sync(0xffffffffu, rs, o, 16);
            l_i[i] = l_i[i] * corr + rs;
#pragma unroll
            for (int j = 0; j < 4; j++) oacc[i][j] *= corr;
        }

        __syncthreads();
#pragma unroll
        for (int i = 0; i < 4; i++)
            *(float4*)&KPs[ty * 4 + i][tx * 4] =
                make_float4(s[i][0], s[i][1], s[i][2], s[i][3]);
        __syncthreads();

#pragma unroll 4
        for (int j4 = 0; j4 < 16; j4++) {
            float4 p0 = *(const float4*)&KPs[ty * 4 + 0][j4 * 4];
            float4 p1 = *(const float4*)&KPs[ty * 4 + 1][j4 * 4];
            float4 p2 = *(const float4*)&KPs[ty * 4 + 2][j4 * 4];
            float4 p3 = *(const float4*)&KPs[ty * 4 + 3][j4 * 4];
            float4 v0 = *(const float4*)&Vs[j4 * 4 + 0][tx * 4];
            float4 v1 = *(const float4*)&Vs[j4 * 4 + 1][tx * 4];
            float4 v2 = *(const float4*)&Vs[j4 * 4 + 2][tx * 4];
            float4 v3 = *(const float4*)&Vs[j4 * 4 + 3][tx * 4];

            oacc[0][0] += p0.x * v0.x + p0.y * v1.x + p0.z * v2.x + p0.w * v3.x;
            oacc[0][1] += p0.x * v0.y + p0.y * v1.y + p0.z * v2.y + p0.w * v3.y;
            oacc[0][2] += p0.x * v0.z + p0.y * v1.z + p0.z * v2.z + p0.w * v3.z;
            oacc[0][3] += p0.x * v0.w + p0.y * v1.w + p0.z * v2.w + p0.w * v3.w;

            oacc[1][0] += p1.x * v0.x + p1.y * v1.x + p1.z * v2.x + p1.w * v3.x;
            oacc[1][1] += p1.x * v0.y + p1.y * v1.y + p1.z * v2.y + p1.w * v3.y;
            oacc[1][2] += p1.x * v0.z + p1.y * v1.z + p1.z * v2.z + p1.w * v3.z;
            oacc[1][3] += p1.x * v0.w + p1.y * v1.w + p1.z * v2.w + p1.w * v3.w;

            oacc[2][0] += p2.x * v0.x + p2.y * v1.x + p2.z * v2.x + p2.w * v3.x;
            oacc[2][1] += p2.x * v0.y + p2.y * v1.y + p2.z * v2.y + p2.w * v3.y;
            oacc[2][2] += p2.x * v0.z + p2.y * v1.z + p2.z * v2.z + p2.w * v3.z;
            oacc[2][3] += p2.x * v0.w + p2.y * v1.w + p2.z * v2.w + p2.w * v3.w;

            oacc[3][0] += p3.x * v0.x + p3.y * v1.x + p3.z * v2.x + p3.w * v3.x;
            oacc[3][1] += p3.x * v0.y + p3.y * v1.y + p3.z * v2.y + p3.w * v3.y;
            oacc[3][2] += p3.x * v0.z + p3.y * v1.z + p3.z * v2.z + p3.w * v3.z;
            oacc[3][3] += p3.x * v0.w + p3.y * v1.w + p3.z * v2.w + p3.w * v3.w;
        }
        __syncthreads();
    }

    float* Og = g_O + ((size_t)(b * Nseq) + qb * 64 + ty * 4) * Dmod + h * HD + tx * 4;
#pragma unroll
    for (int i = 0; i < 4; i++) {
        float inv = 1.0f / l_i[i];
        *(float4*)(Og + (size_t)i * Dmod) =
            make_float4(oacc[i][0] * inv, oacc[i][1] * inv,
                        oacc[i][2] * inv, oacc[i][3] * inv);
    }
}

// ---------------------------------------------------------------------------
extern "C" void kernel_launch(void* const* d_in, const int* in_sizes, int n_in,
                              void* d_out, int out_size)
{
    const float* x   = (const float*)d_in[0];
    const float* Bg  = (const float*)d_in[1];
    const float* Wq  = (const float*)d_in[2];
    const float* bq  = (const float*)d_in[3];
    const float* Wk  = (const float*)d_in[4];
    const float* bk  = (const float*)d_in[5];
    const float* Wv  = (const float*)d_in[6];
    const float* bv  = (const float*)d_in[7];
    const float* Wo  = (const float*)d_in[8];
    const float* bo  = (const float*)d_in[9];
    const float* lam = (const float*)d_in[10];
    float* out = (float*)d_out;

    // Split inputs to bf16 hi/lo
    conv_split_x<<<4096, 256>>>((const float4*)x);
    conv_w<<<dim3(32, 32, 4), dim3(32, 8)>>>(Wq, Wk, Wv, Wo);

    // QKV projections (HMMA bf16x3)
    mma_qkv<<<dim3(8, 32, 3), 256>>>(bq, bk, bv);

    // Attention
    attn_kernel<<<dim3(32, 16, 2), 256>>>(Bg, lam);

    // Output projection
    conv_split_o<<<4096, 256>>>();
    mma_out<<<dim3(8, 32, 1), 256>>>(bo, out);
}

// round 4
// speedup vs baseline: 2.1353x; 1.6496x over previous
#include <cuda_runtime.h>
#include <cuda_bf16.h>
#include <cstdint>
#include <math.h>

// Problem constants
#define Bdim 2
#define Nseq 2048
#define Dmod 1024
#define Hn   16
#define HD   64

// ---------------------------------------------------------------------------
// Scratch (alloc-free rule: __device__ globals)
// ---------------------------------------------------------------------------
#define QKV_ELEMS ((size_t)Bdim * Hn * Nseq * HD)
__device__ __nv_bfloat16 g_Qh[QKV_ELEMS], g_Ql[QKV_ELEMS];   // [b][h][n][d]
__device__ __nv_bfloat16 g_Kh[QKV_ELEMS], g_Kl[QKV_ELEMS];
__device__ __nv_bfloat16 g_Vh[QKV_ELEMS], g_Vl[QKV_ELEMS];
__device__ __nv_bfloat16 g_Vth[QKV_ELEMS], g_Vtl[QKV_ELEMS]; // [b][h][d][n]

__device__ __nv_bfloat16 g_xh[(size_t)4096 * 1024];
__device__ __nv_bfloat16 g_xl[(size_t)4096 * 1024];
__device__ __nv_bfloat16 g_oh[(size_t)4096 * 1024];          // attn out [b][n][1024]
__device__ __nv_bfloat16 g_ol[(size_t)4096 * 1024];
__device__ __nv_bfloat16 g_wth[4][(size_t)1024 * 1024];      // W^T [n][k]
__device__ __nv_bfloat16 g_wtl[4][(size_t)1024 * 1024];

// ---------------------------------------------------------------------------
// HMMA m16n8k16 bf16 -> f32
// ---------------------------------------------------------------------------
__device__ __forceinline__ void mma_bf16(float (&d)[4],
                                         const uint32_t (&a)[4],
                                         const uint32_t (&b)[2])
{
    asm volatile(
        "mma.sync.aligned.m16n8k16.row.col.f32.bf16.bf16.f32 "
        "{%0,%1,%2,%3}, {%4,%5,%6,%7}, {%8,%9}, {%0,%1,%2,%3};"
        : "+f"(d[0]), "+f"(d[1]), "+f"(d[2]), "+f"(d[3])
        : "r"(a[0]), "r"(a[1]), "r"(a[2]), "r"(a[3]),
          "r"(b[0]), "r"(b[1]));
}

__device__ __forceinline__ uint32_t pack2(float a, float b)
{
    return (uint32_t)__bfloat16_as_ushort(__float2bfloat16_rn(a)) |
           ((uint32_t)__bfloat16_as_ushort(__float2bfloat16_rn(b)) << 16);
}

// split v -> hi bf16 + residual float
__device__ __forceinline__ void split1(float v, float& hf, float& lf)
{
    __nv_bfloat16 h = __float2bfloat16_rn(v);
    hf = __bfloat162float(h);
    lf = v - hf;
}

// ---------------------------------------------------------------------------
// Conversions
// ---------------------------------------------------------------------------
__device__ __forceinline__ void split4(float4 v, ushort4& H, ushort4& L)
{
    __nv_bfloat16 h0 = __float2bfloat16_rn(v.x);
    __nv_bfloat16 h1 = __float2bfloat16_rn(v.y);
    __nv_bfloat16 h2 = __float2bfloat16_rn(v.z);
    __nv_bfloat16 h3 = __float2bfloat16_rn(v.w);
    H = {__bfloat16_as_ushort(h0), __bfloat16_as_ushort(h1),
         __bfloat16_as_ushort(h2), __bfloat16_as_ushort(h3)};
    L = {__bfloat16_as_ushort(__float2bfloat16_rn(v.x - __bfloat162float(h0))),
         __bfloat16_as_ushort(__float2bfloat16_rn(v.y - __bfloat162float(h1))),
         __bfloat16_as_ushort(__float2bfloat16_rn(v.z - __bfloat162float(h2))),
         __bfloat16_as_ushort(__float2bfloat16_rn(v.w - __bfloat162float(h3)))};
}

__global__ void conv_split_x(const float4* __restrict__ src)
{
    int i = blockIdx.x * 256 + threadIdx.x;
    ushort4 H, L;
    split4(src[i], H, L);
    ((ushort4*)g_xh)[i] = H;
    ((ushort4*)g_xl)[i] = L;
}

__global__ void conv_w(const float* __restrict__ Wq, const float* __restrict__ Wk,
                       const float* __restrict__ Wv, const float* __restrict__ Wo)
{
    __shared__ float t[32][33];
    int z = blockIdx.z;
    const float* W = (z == 0) ? Wq : (z == 1) ? Wk : (z == 2) ? Wv : Wo;
    int n0 = blockIdx.x * 32, k0 = blockIdx.y * 32;
    int tx = threadIdx.x, ty = threadIdx.y;
#pragma unroll
    for (int j = 0; j < 32; j += 8)
        t[ty + j][tx] = W[(size_t)(k0 + ty + j) * 1024 + n0 + tx];
    __syncthreads();
#pragma unroll
    for (int j = 0; j < 32; j += 8) {
        float v = t[tx][ty + j];
        __nv_bfloat16 h = __float2bfloat16_rn(v);
        __nv_bfloat16 l = __float2bfloat16_rn(v - __bfloat162float(h));
        size_t idx = (size_t)(n0 + ty + j) * 1024 + k0 + tx;
        g_wth[z][idx] = h;
        g_wtl[z][idx] = l;
    }
}

// V [bh][n][d] -> Vt [bh][d][n], hi+lo
__global__ void transpose_v()
{
    __shared__ __nv_bfloat16 th[32][33], tl[32][33];
    int bh = blockIdx.z;
    int n0 = blockIdx.x * 32, d0 = blockIdx.y * 32;
    int tx = threadIdx.x, ty = threadIdx.y;
#pragma unroll
    for (int j = 0; j < 32; j += 8) {
        size_t src = ((size_t)bh * 2048 + n0 + ty + j) * 64 + d0 + tx;
        th[ty + j][tx] = g_Vh[src];
        tl[ty + j][tx] = g_Vl[src];
    }
    __syncthreads();
#pragma unroll
    for (int j = 0; j < 32; j += 8) {
        size_t dst = ((size_t)bh * 64 + d0 + ty + j) * 2048 + n0 + tx;
        g_Vth[dst] = th[tx][ty + j];
        g_Vtl[dst] = tl[tx][ty + j];
    }
}

// ---------------------------------------------------------------------------
// HMMA bf16x3 GEMM: C[4096,1024] = A @ B^T + bias   (B stored [n][k])
// ---------------------------------------------------------------------------
#define TSTRIDE 20

template <bool HEAD>
__device__ __forceinline__ void mma_gemm_body(const __nv_bfloat16* __restrict__ Ahi,
                                              const __nv_bfloat16* __restrict__ Alo,
                                              const __nv_bfloat16* __restrict__ Bhi,
                                              const __nv_bfloat16* __restrict__ Blo,
                                              const float* __restrict__ bias,
                                              float* __restrict__ out,
                                              __nv_bfloat16* __restrict__ outH,
                                              __nv_bfloat16* __restrict__ outL)
{
    __shared__ uint32_t Ah[128 * TSTRIDE];
    __shared__ uint32_t Al[128 * TSTRIDE];
    __shared__ uint32_t Bh[128 * TSTRIDE];
    __shared__ uint32_t Bl[128 * TSTRIDE];

    const int tid = threadIdx.x;
    const int wid = tid >> 5;
    const int lid = tid & 31;
    const int wm  = wid & 3;
    const int wn  = wid >> 2;
    const int gq  = lid >> 2;
    const int tq  = lid & 3;
    const int m0 = blockIdx.y * 128;
    const int n0 = blockIdx.x * 128;

    float acc[2][8][4];
#pragma unroll
    for (int mt = 0; mt < 2; mt++)
#pragma unroll
        for (int nt = 0; nt < 8; nt++)
#pragma unroll
            for (int e = 0; e < 4; e++) acc[mt][nt][e] = 0.f;

    for (int kt = 0; kt < 1024; kt += 32) {
#pragma unroll
        for (int q = 0; q < 2; q++) {
            int u = tid * 2 + q;
            int row = u >> 2;
            int c4 = u & 3;
            size_t ga = (size_t)(m0 + row) * 1024 + kt;
            size_t gb = (size_t)(n0 + row) * 1024 + kt;
            *(uint4*)&Ah[row * TSTRIDE + c4 * 4] = ((const uint4*)(Ahi + ga))[c4];
            *(uint4*)&Al[row * TSTRIDE + c4 * 4] = ((const uint4*)(Alo + ga))[c4];
            *(uint4*)&Bh[row * TSTRIDE + c4 * 4] = ((const uint4*)(Bhi + gb))[c4];
            *(uint4*)&Bl[row * TSTRIDE + c4 * 4] = ((const uint4*)(Blo + gb))[c4];
        }
        __syncthreads();

#pragma unroll
        for (int ks = 0; ks < 2; ks++) {
            const int c0 = ks * 8;
            uint32_t bh[8][2], bl[8][2];
#pragma unroll
            for (int nt = 0; nt < 8; nt++) {
                int brow = (wn * 64 + nt * 8 + gq) * TSTRIDE + c0 + tq;
                bh[nt][0] = Bh[brow];
                bh[nt][1] = Bh[brow + 4];
                bl[nt][0] = Bl[brow];
                bl[nt][1] = Bl[brow + 4];
            }
#pragma unroll
            for (int mt = 0; mt < 2; mt++) {
                int ar0 = (wm * 32 + mt * 16 + gq) * TSTRIDE + c0 + tq;
                int ar1 = ar0 + 8 * TSTRIDE;
                uint32_t ah[4], al[4];
                ah[0] = Ah[ar0];     ah[1] = Ah[ar1];
                ah[2] = Ah[ar0 + 4]; ah[3] = Ah[ar1 + 4];
                al[0] = Al[ar0];     al[1] = Al[ar1];
                al[2] = Al[ar0 + 4]; al[3] = Al[ar1 + 4];
#pragma unroll
                for (int nt = 0; nt < 8; nt++) {
                    mma_bf16(acc[mt][nt], ah, bh[nt]);
                    mma_bf16(acc[mt][nt], ah, bl[nt]);
                    mma_bf16(acc[mt][nt], al, bh[nt]);
                }
            }
        }
        __syncthreads();
    }

#pragma unroll
    for (int mt = 0; mt < 2; mt++) {
#pragma unroll
        for (int nt = 0; nt < 8; nt++) {
            int R = m0 + wm * 32 + mt * 16 + gq;
            int C = n0 + wn * 64 + nt * 8 + tq * 2;
            float b0 = bias[C], b1 = bias[C + 1];
#pragma unroll
            for (int half = 0; half < 2; half++) {
                int r = R + half * 8;
                float v0 = acc[mt][nt][half * 2 + 0] + b0;
                float v1 = acc[mt][nt][half * 2 + 1] + b1;
                if (HEAD) {
                    // write bf16 hi/lo in [b][h][n][d]
                    int b = r >> 11;
                    int n = r & 2047;
                    int hh = C >> 6;
                    int d = C & 63;
                    float h0, l0, h1, l1;
                    split1(v0, h0, l0);
                    split1(v1, h1, l1);
                    size_t ui = (((size_t)(b * Hn + hh)) * 2048 + n) * 32 + (d >> 1);
                    ((uint32_t*)outH)[ui] = pack2(h0, h1);
                    ((uint32_t*)outL)[ui] = pack2(l0, l1);
                } else {
                    *(float2*)(out + (size_t)r * 1024 + C) = make_float2(v0, v1);
                }
            }
        }
    }
}

__global__ void __launch_bounds__(256, 2)
mma_qkv(const float* __restrict__ bq, const float* __restrict__ bk,
        const float* __restrict__ bv)
{
    int z = blockIdx.z;
    const float* bias = (z == 0) ? bq : (z == 1) ? bk : bv;
    __nv_bfloat16* oh = (z == 0) ? g_Qh : (z == 1) ? g_Kh : g_Vh;
    __nv_bfloat16* ol = (z == 0) ? g_Ql : (z == 1) ? g_Kl : g_Vl;
    mma_gemm_body<true>(g_xh, g_xl, g_wth[z], g_wtl[z], bias, nullptr, oh, ol);
}

__global__ void __launch_bounds__(256, 2)
mma_out(const float* __restrict__ bo, float* __restrict__ out)
{
    mma_gemm_body<false>(g_oh, g_ol, g_wth[3], g_wtl[3], bo, out, nullptr, nullptr);
}

// ---------------------------------------------------------------------------
// HMMA flash attention. BQ=128, BK=32, 8 warps (16 rows each).
// Smem: Q hi/lo 32KB + K hi/lo 8KB + Vt(hi|lo packed) 8KB = 48KB.
// XOR swizzle: word' = word ^ ((row&7)<<2) -> conflict-free fragment loads.
// ---------------------------------------------------------------------------
#define QSW(r, w) (((r) * 32) + ((w) ^ (((r) & 7) << 2)))

__global__ void __launch_bounds__(256, 2)
attn_mma(const float* __restrict__ Bg, const float* __restrict__ lam_p)
{
    __shared__ uint32_t sQh[128 * 32];
    __shared__ uint32_t sQl[128 * 32];
    __shared__ uint32_t sKh[32 * 32];
    __shared__ uint32_t sKl[32 * 32];
    __shared__ uint32_t sVt[64 * 32];   // per row: words 0-15 hi, 16-31 lo

    const int tid = threadIdx.x;
    const int wm  = tid >> 5;
    const int lid = tid & 31;
    const int gq  = lid >> 2;
    const int tq  = lid & 3;
    const int qb = blockIdx.x;
    const int h  = blockIdx.y;
    const int b  = blockIdx.z;
    const int bh = b * Hn + h;
    const int q0 = qb * 128;

    const float lam = __ldg(lam_p);
    const float scale = 0.125f;

    // Load Q tile (rows q0..q0+127)
    {
        const __nv_bfloat16* Qhg = g_Qh + ((size_t)bh * 2048 + q0) * 64;
        const __nv_bfloat16* Qlg = g_Ql + ((size_t)bh * 2048 + q0) * 64;
#pragma unroll
        for (int i = 0; i < 4; i++) {
            int u = tid + i * 256;
            int row = u >> 3;
            int c4 = u & 7;
            int w = (4 * c4) ^ ((row & 7) << 2);
            *(uint4*)&sQh[row * 32 + w] = ((const uint4*)(Qhg + (size_t)row * 64))[c4];
            *(uint4*)&sQl[row * 32 + w] = ((const uint4*)(Qlg + (size_t)row * 64))[c4];
        }
    }

    float m_i[2] = {-1e30f, -1e30f};
    float l_i[2] = {0.f, 0.f};
    float o[8][4];
#pragma unroll
    for (int nt = 0; nt < 8; nt++)
#pragma unroll
        for (int e = 0; e < 4; e++) o[nt][e] = 0.f;

    const float* Bgb = Bg + (size_t)b * Nseq * Nseq;
    const int qrow = q0 + wm * 16 + gq;
    const int r0 = wm * 16 + gq;

    for (int kb = 0; kb < 64; kb++) {
        __syncthreads();
        // Load K tile (32 rows) and Vt tile (64 rows, hi|lo)
        {
            int row = tid >> 3;
            int c4 = tid & 7;
            int w = (4 * c4) ^ ((row & 7) << 2);
            const __nv_bfloat16* Khg = g_Kh + ((size_t)bh * 2048 + kb * 32 + row) * 64;
            const __nv_bfloat16* Klg = g_Kl + ((size_t)bh * 2048 + kb * 32 + row) * 64;
            sKh[row * 32 + w] = 0;  // dummy to keep compiler honest? no—overwritten below
            *(uint4*)&sKh[row * 32 + w] = ((const uint4*)Khg)[c4];
            *(uint4*)&sKl[row * 32 + w] = ((const uint4*)Klg)[c4];

            int vrow = tid >> 2;
            int vc4 = tid & 3;
            const __nv_bfloat16* Vhg = g_Vth + ((size_t)bh * 64 + vrow) * 2048 + kb * 32;
            const __nv_bfloat16* Vlg = g_Vtl + ((size_t)bh * 64 + vrow) * 2048 + kb * 32;
            int wh = (4 * vc4) ^ ((vrow & 7) << 2);
            int wl = (16 + 4 * vc4) ^ ((vrow & 7) << 2);
            *(uint4*)&sVt[vrow * 32 + wh] = ((const uint4*)Vhg)[vc4];
            *(uint4*)&sVt[vrow * 32 + wl] = ((const uint4*)Vlg)[vc4];
        }
        __syncthreads();

        // S = Q K^T  (4 n-tiles of 8 cols, 4 k-steps over d)
        float s[4][4];
#pragma unroll
        for (int nt = 0; nt < 4; nt++)
#pragma unroll
            for (int e = 0; e < 4; e++) s[nt][e] = 0.f;

#pragma unroll
        for (int kt = 0; kt < 4; kt++) {
            uint32_t ah[4], al[4];
            ah[0] = sQh[QSW(r0,     8 * kt + tq)];
            ah[1] = sQh[QSW(r0 + 8, 8 * kt + tq)];
            ah[2] = sQh[QSW(r0,     8 * kt + 4 + tq)];
            ah[3] = sQh[QSW(r0 + 8, 8 * kt + 4 + tq)];
            al[0] = sQl[QSW(r0,     8 * kt + tq)];
            al[1] = sQl[QSW(r0 + 8, 8 * kt + tq)];
            al[2] = sQl[QSW(r0,     8 * kt + 4 + tq)];
            al[3] = sQl[QSW(r0 + 8, 8 * kt + 4 + tq)];
#pragma unroll
            for (int nt = 0; nt < 4; nt++) {
                int kr = 8 * nt + gq;
                uint32_t kh[2], kl[2];
                kh[0] = sKh[QSW(kr, 8 * kt + tq)];
                kh[1] = sKh[QSW(kr, 8 * kt + 4 + tq)];
                kl[0] = sKl[QSW(kr, 8 * kt + tq)];
                kl[1] = sKl[QSW(kr, 8 * kt + 4 + tq)];
                mma_bf16(s[nt], ah, kh);
                mma_bf16(s[nt], ah, kl);
                mma_bf16(s[nt], al, kh);
            }
        }

        // scale + Gaussian bias
#pragma unroll
        for (int nt = 0; nt < 4; nt++) {
#pragma unroll
            for (int half = 0; half < 2; half++) {
                int row = qrow + half * 8;
                float2 bg = *(const float2*)(Bgb + (size_t)row * 2048 +
                                             kb * 32 + nt * 8 + tq * 2);
                s[nt][half * 2 + 0] = s[nt][half * 2 + 0] * scale + lam * bg.x;
                s[nt][half * 2 + 1] = s[nt][half * 2 + 1] * scale + lam * bg.y;
            }
        }

        // online softmax (row lives in a lane-quad)
#pragma unroll
        for (int half = 0; half < 2; half++) {
            float mx = -1e30f;
#pragma unroll
            for (int nt = 0; nt < 4; nt++)
                mx = fmaxf(mx, fmaxf(s[nt][half * 2], s[nt][half * 2 + 1]));
            mx = fmaxf(mx, __shfl_xor_sync(0xffffffffu, mx, 1));
            mx = fmaxf(mx, __shfl_xor_sync(0xffffffffu, mx, 2));
            float mn = fmaxf(m_i[half], mx);
            float corr = __expf(m_i[half] - mn);
            m_i[half] = mn;
            float rs = 0.f;
#pragma unroll
            for (int nt = 0; nt < 4; nt++) {
                s[nt][half * 2]     = __expf(s[nt][half * 2] - mn);
                s[nt][half * 2 + 1] = __expf(s[nt][half * 2 + 1] - mn);
                rs += s[nt][half * 2] + s[nt][half * 2 + 1];
            }
            rs += __shfl_xor_sync(0xffffffffu, rs, 1);
            rs += __shfl_xor_sync(0xffffffffu, rs, 2);
            l_i[half] = l_i[half] * corr + rs;
#pragma unroll
            for (int nt = 0; nt < 8; nt++) {
                o[nt][half * 2]     *= corr;
                o[nt][half * 2 + 1] *= corr;
            }
        }

        // O += P V  (P from registers; 2 k-steps over j, 8 n-tiles over d)
#pragma unroll
        for (int kt = 0; kt < 2; kt++) {
            float h0, l0, h1, l1, h2, l2, h3, l3;
            uint32_t ph[4], pl[4];
            split1(s[2 * kt][0], h0, l0); split1(s[2 * kt][1], h1, l1);
            split1(s[2 * kt][2], h2, l2); split1(s[2 * kt][3], h3, l3);
            ph[0] = pack2(h0, h1); pl[0] = pack2(l0, l1);
            ph[1] = pack2(h2, h3); pl[1] = pack2(l2, l3);
            split1(s[2 * kt + 1][0], h0, l0); split1(s[2 * kt + 1][1], h1, l1);
            split1(s[2 * kt + 1][2], h2, l2); split1(s[2 * kt + 1][3], h3, l3);
            ph[2] = pack2(h0, h1); pl[2] = pack2(l0, l1);
            ph[3] = pack2(h2, h3); pl[3] = pack2(l2, l3);
#pragma unroll
            for (int nt = 0; nt < 8; nt++) {
                int vr = 8 * nt + gq;
                uint32_t vh[2], vl[2];
                vh[0] = sVt[QSW(vr, 8 * kt + tq)];
                vh[1] = sVt[QSW(vr, 8 * kt + 4 + tq)];
                vl[0] = sVt[QSW(vr, 16 + 8 * kt + tq)];
                vl[1] = sVt[QSW(vr, 16 + 8 * kt + 4 + tq)];
                mma_bf16(o[nt], ph, vh);
                mma_bf16(o[nt], ph, vl);
                mma_bf16(o[nt], pl, vh);
            }
        }
    }

    // Epilogue: normalize, split hi/lo, write to g_oh/g_ol [b][n][1024]
    float inv0 = 1.0f / l_i[0];
    float inv1 = 1.0f / l_i[1];
#pragma unroll
    for (int nt = 0; nt < 8; nt++) {
#pragma unroll
        for (int half = 0; half < 2; half++) {
            float inv = half ? inv1 : inv0;
            int row = qrow + half * 8;
            float v0 = o[nt][half * 2 + 0] * inv;
            float v1 = o[nt][half * 2 + 1] * inv;
            float h0, l0, h1, l1;
            split1(v0, h0, l0);
            split1(v1, h1, l1);
            size_t ui = ((size_t)(b * 2048) + row) * 512 + h * 32 + nt * 4 + tq;
            ((uint32_t*)g_oh)[ui] = pack2(h0, h1);
            ((uint32_t*)g_ol)[ui] = pack2(l0, l1);
        }
    }
}

// ---------------------------------------------------------------------------
extern "C" void kernel_launch(void* const* d_in, const int* in_sizes, int n_in,
                              void* d_out, int out_size)
{
    const float* x   = (const float*)d_in[0];
    const float* Bg  = (const float*)d_in[1];
    const float* Wq  = (const float*)d_in[2];
    const float* bq  = (const float*)d_in[3];
    const float* Wk  = (const float*)d_in[4];
    const float* bk  = (const float*)d_in[5];
    const float* Wv  = (const float*)d_in[6];
    const float* bv  = (const float*)d_in[7];
    const float* Wo  = (const float*)d_in[8];
    const float* bo  = (const float*)d_in[9];
    const float* lam = (const float*)d_in[10];
    float* out = (float*)d_out;

    conv_split_x<<<4096, 256>>>((const float4*)x);
    conv_w<<<dim3(32, 32, 4), dim3(32, 8)>>>(Wq, Wk, Wv, Wo);

    mma_qkv<<<dim3(8, 32, 3), 256>>>(bq, bk, bv);
    transpose_v<<<dim3(64, 2, 32), dim3(32, 8)>>>();

    attn_mma<<<dim3(16, 16, 2), 256>>>(Bg, lam);

    mma_out<<<dim3(8, 32, 1), 256>>>(bo, out);
}

// round 5
// speedup vs baseline: 2.1987x; 1.0297x over previous
#include <cuda_runtime.h>
#include <cuda_bf16.h>
#include <cstdint>
#include <math.h>

// Problem constants
#define Bdim 2
#define Nseq 2048
#define Dmod 1024
#define Hn   16
#define HD   64

// ---------------------------------------------------------------------------
// Scratch (alloc-free rule: __device__ globals)
// ---------------------------------------------------------------------------
#define QKV_ELEMS ((size_t)Bdim * Hn * Nseq * HD)
__device__ __nv_bfloat16 g_Qh[QKV_ELEMS], g_Ql[QKV_ELEMS];   // [b][h][n][d]
__device__ __nv_bfloat16 g_Kh[QKV_ELEMS], g_Kl[QKV_ELEMS];
__device__ __nv_bfloat16 g_Vh[QKV_ELEMS], g_Vl[QKV_ELEMS];
__device__ __nv_bfloat16 g_Vth[QKV_ELEMS], g_Vtl[QKV_ELEMS]; // [b][h][d][n]

__device__ __nv_bfloat16 g_xh[(size_t)4096 * 1024];
__device__ __nv_bfloat16 g_xl[(size_t)4096 * 1024];
__device__ __nv_bfloat16 g_oh[(size_t)4096 * 1024];          // attn out [b][n][1024]
__device__ __nv_bfloat16 g_ol[(size_t)4096 * 1024];
__device__ __nv_bfloat16 g_wth[4][(size_t)1024 * 1024];      // W^T [n][k]
__device__ __nv_bfloat16 g_wtl[4][(size_t)1024 * 1024];

// ---------------------------------------------------------------------------
// HMMA m16n8k16 bf16 -> f32
// ---------------------------------------------------------------------------
__device__ __forceinline__ void mma_bf16(float (&d)[4],
                                         const uint32_t (&a)[4],
                                         const uint32_t (&b)[2])
{
    asm volatile(
        "mma.sync.aligned.m16n8k16.row.col.f32.bf16.bf16.f32 "
        "{%0,%1,%2,%3}, {%4,%5,%6,%7}, {%8,%9}, {%0,%1,%2,%3};"
        : "+f"(d[0]), "+f"(d[1]), "+f"(d[2]), "+f"(d[3])
        : "r"(a[0]), "r"(a[1]), "r"(a[2]), "r"(a[3]),
          "r"(b[0]), "r"(b[1]));
}

__device__ __forceinline__ uint32_t pack2(float a, float b)
{
    return (uint32_t)__bfloat16_as_ushort(__float2bfloat16_rn(a)) |
           ((uint32_t)__bfloat16_as_ushort(__float2bfloat16_rn(b)) << 16);
}

__device__ __forceinline__ void split1(float v, float& hf, float& lf)
{
    __nv_bfloat16 h = __float2bfloat16_rn(v);
    hf = __bfloat162float(h);
    lf = v - hf;
}

// ---------------------------------------------------------------------------
// Conversions
// ---------------------------------------------------------------------------
__device__ __forceinline__ void split4(float4 v, ushort4& H, ushort4& L)
{
    __nv_bfloat16 h0 = __float2bfloat16_rn(v.x);
    __nv_bfloat16 h1 = __float2bfloat16_rn(v.y);
    __nv_bfloat16 h2 = __float2bfloat16_rn(v.z);
    __nv_bfloat16 h3 = __float2bfloat16_rn(v.w);
    H = {__bfloat16_as_ushort(h0), __bfloat16_as_ushort(h1),
         __bfloat16_as_ushort(h2), __bfloat16_as_ushort(h3)};
    L = {__bfloat16_as_ushort(__float2bfloat16_rn(v.x - __bfloat162float(h0))),
         __bfloat16_as_ushort(__float2bfloat16_rn(v.y - __bfloat162float(h1))),
         __bfloat16_as_ushort(__float2bfloat16_rn(v.z - __bfloat162float(h2))),
         __bfloat16_as_ushort(__float2bfloat16_rn(v.w - __bfloat162float(h3)))};
}

__global__ void conv_split_x(const float4* __restrict__ src)
{
    int i = blockIdx.x * 256 + threadIdx.x;
    ushort4 H, L;
    split4(src[i], H, L);
    ((ushort4*)g_xh)[i] = H;
    ((ushort4*)g_xl)[i] = L;
}

__global__ void conv_w(const float* __restrict__ Wq, const float* __restrict__ Wk,
                       const float* __restrict__ Wv, const float* __restrict__ Wo)
{
    __shared__ float t[32][33];
    int z = blockIdx.z;
    const float* W = (z == 0) ? Wq : (z == 1) ? Wk : (z == 2) ? Wv : Wo;
    int n0 = blockIdx.x * 32, k0 = blockIdx.y * 32;
    int tx = threadIdx.x, ty = threadIdx.y;
#pragma unroll
    for (int j = 0; j < 32; j += 8)
        t[ty + j][tx] = W[(size_t)(k0 + ty + j) * 1024 + n0 + tx];
    __syncthreads();
#pragma unroll
    for (int j = 0; j < 32; j += 8) {
        float v = t[tx][ty + j];
        __nv_bfloat16 h = __float2bfloat16_rn(v);
        __nv_bfloat16 l = __float2bfloat16_rn(v - __bfloat162float(h));
        size_t idx = (size_t)(n0 + ty + j) * 1024 + k0 + tx;
        g_wth[z][idx] = h;
        g_wtl[z][idx] = l;
    }
}

// V [bh][n][d] -> Vt [bh][d][n], hi+lo
__global__ void transpose_v()
{
    __shared__ __nv_bfloat16 th[32][33], tl[32][33];
    int bh = blockIdx.z;
    int n0 = blockIdx.x * 32, d0 = blockIdx.y * 32;
    int tx = threadIdx.x, ty = threadIdx.y;
#pragma unroll
    for (int j = 0; j < 32; j += 8) {
        size_t src = ((size_t)bh * 2048 + n0 + ty + j) * 64 + d0 + tx;
        th[ty + j][tx] = g_Vh[src];
        tl[ty + j][tx] = g_Vl[src];
    }
    __syncthreads();
#pragma unroll
    for (int j = 0; j < 32; j += 8) {
        size_t dst = ((size_t)bh * 64 + d0 + ty + j) * 2048 + n0 + tx;
        g_Vth[dst] = th[tx][ty + j];
        g_Vtl[dst] = tl[tx][ty + j];
    }
}

// ---------------------------------------------------------------------------
// HMMA bf16x3 GEMM: C[4096,1024] = A @ B^T + bias   (B stored [n][k])
// ---------------------------------------------------------------------------
#define TSTRIDE 20

template <bool HEAD>
__device__ __forceinline__ void mma_gemm_body(const __nv_bfloat16* __restrict__ Ahi,
                                              const __nv_bfloat16* __restrict__ Alo,
                                              const __nv_bfloat16* __restrict__ Bhi,
                                              const __nv_bfloat16* __restrict__ Blo,
                                              const float* __restrict__ bias,
                                              float* __restrict__ out,
                                              __nv_bfloat16* __restrict__ outH,
                                              __nv_bfloat16* __restrict__ outL)
{
    __shared__ uint32_t Ah[128 * TSTRIDE];
    __shared__ uint32_t Al[128 * TSTRIDE];
    __shared__ uint32_t Bh[128 * TSTRIDE];
    __shared__ uint32_t Bl[128 * TSTRIDE];

    const int tid = threadIdx.x;
    const int wid = tid >> 5;
    const int lid = tid & 31;
    const int wm  = wid & 3;
    const int wn  = wid >> 2;
    const int gq  = lid >> 2;
    const int tq  = lid & 3;
    const int m0 = blockIdx.y * 128;
    const int n0 = blockIdx.x * 128;

    float acc[2][8][4];
#pragma unroll
    for (int mt = 0; mt < 2; mt++)
#pragma unroll
        for (int nt = 0; nt < 8; nt++)
#pragma unroll
            for (int e = 0; e < 4; e++) acc[mt][nt][e] = 0.f;

    for (int kt = 0; kt < 1024; kt += 32) {
#pragma unroll
        for (int q = 0; q < 2; q++) {
            int u = tid * 2 + q;
            int row = u >> 2;
            int c4 = u & 3;
            size_t ga = (size_t)(m0 + row) * 1024 + kt;
            size_t gb = (size_t)(n0 + row) * 1024 + kt;
            *(uint4*)&Ah[row * TSTRIDE + c4 * 4] = ((const uint4*)(Ahi + ga))[c4];
            *(uint4*)&Al[row * TSTRIDE + c4 * 4] = ((const uint4*)(Alo + ga))[c4];
            *(uint4*)&Bh[row * TSTRIDE + c4 * 4] = ((const uint4*)(Bhi + gb))[c4];
            *(uint4*)&Bl[row * TSTRIDE + c4 * 4] = ((const uint4*)(Blo + gb))[c4];
        }
        __syncthreads();

#pragma unroll
        for (int ks = 0; ks < 2; ks++) {
            const int c0 = ks * 8;
            uint32_t bh[8][2], bl[8][2];
#pragma unroll
            for (int nt = 0; nt < 8; nt++) {
                int brow = (wn * 64 + nt * 8 + gq) * TSTRIDE + c0 + tq;
                bh[nt][0] = Bh[brow];
                bh[nt][1] = Bh[brow + 4];
                bl[nt][0] = Bl[brow];
                bl[nt][1] = Bl[brow + 4];
            }
#pragma unroll
            for (int mt = 0; mt < 2; mt++) {
                int ar0 = (wm * 32 + mt * 16 + gq) * TSTRIDE + c0 + tq;
                int ar1 = ar0 + 8 * TSTRIDE;
                uint32_t ah[4], al[4];
                ah[0] = Ah[ar0];     ah[1] = Ah[ar1];
                ah[2] = Ah[ar0 + 4]; ah[3] = Ah[ar1 + 4];
                al[0] = Al[ar0];     al[1] = Al[ar1];
                al[2] = Al[ar0 + 4]; al[3] = Al[ar1 + 4];
#pragma unroll
                for (int nt = 0; nt < 8; nt++) {
                    mma_bf16(acc[mt][nt], ah, bh[nt]);
                    mma_bf16(acc[mt][nt], ah, bl[nt]);
                    mma_bf16(acc[mt][nt], al, bh[nt]);
                }
            }
        }
        __syncthreads();
    }

#pragma unroll
    for (int mt = 0; mt < 2; mt++) {
#pragma unroll
        for (int nt = 0; nt < 8; nt++) {
            int R = m0 + wm * 32 + mt * 16 + gq;
            int C = n0 + wn * 64 + nt * 8 + tq * 2;
            float b0 = bias[C], b1 = bias[C + 1];
#pragma unroll
            for (int half = 0; half < 2; half++) {
                int r = R + half * 8;
                float v0 = acc[mt][nt][half * 2 + 0] + b0;
                float v1 = acc[mt][nt][half * 2 + 1] + b1;
                if (HEAD) {
                    int b = r >> 11;
                    int n = r & 2047;
                    int hh = C >> 6;
                    int d = C & 63;
                    float h0, l0, h1, l1;
                    split1(v0, h0, l0);
                    split1(v1, h1, l1);
                    size_t ui = (((size_t)(b * Hn + hh)) * 2048 + n) * 32 + (d >> 1);
                    ((uint32_t*)outH)[ui] = pack2(h0, h1);
                    ((uint32_t*)outL)[ui] = pack2(l0, l1);
                } else {
                    *(float2*)(out + (size_t)r * 1024 + C) = make_float2(v0, v1);
                }
            }
        }
    }
}

__global__ void __launch_bounds__(256, 2)
mma_qkv(const float* __restrict__ bq, const float* __restrict__ bk,
        const float* __restrict__ bv)
{
    int z = blockIdx.z;
    const float* bias = (z == 0) ? bq : (z == 1) ? bk : bv;
    __nv_bfloat16* oh = (z == 0) ? g_Qh : (z == 1) ? g_Kh : g_Vh;
    __nv_bfloat16* ol = (z == 0) ? g_Ql : (z == 1) ? g_Kl : g_Vl;
    mma_gemm_body<true>(g_xh, g_xl, g_wth[z], g_wtl[z], bias, nullptr, oh, ol);
}

__global__ void __launch_bounds__(256, 2)
mma_out(const float* __restrict__ bo, float* __restrict__ out)
{
    mma_gemm_body<false>(g_oh, g_ol, g_wth[3], g_wtl[3], bo, out, nullptr, nullptr);
}

// ---------------------------------------------------------------------------
// HMMA flash attention v2. BQ=128, BK=64, 8 warps (16 rows each).
// Q-hi fragments live in registers (loaded once from gmem).
// Smem: Q-lo 16KB + K hi/lo 16KB + Vt hi/lo 16KB = 48KB static.
// XOR swizzle: word' = word ^ ((row&7)<<2) -> conflict-free fragment loads.
// ---------------------------------------------------------------------------
#define QSW(r, w) (((r) * 32) + ((w) ^ (((r) & 7) << 2)))

__global__ void __launch_bounds__(256, 2)
attn_mma(const float* __restrict__ Bg, const float* __restrict__ lam_p)
{
    __shared__ uint32_t sQl[128 * 32];
    __shared__ uint32_t sKh[64 * 32];
    __shared__ uint32_t sKl[64 * 32];
    __shared__ uint32_t sVh[64 * 32];
    __shared__ uint32_t sVl[64 * 32];

    const int tid = threadIdx.x;
    const int wm  = tid >> 5;
    const int lid = tid & 31;
    const int gq  = lid >> 2;
    const int tq  = lid & 3;
    const int qb = blockIdx.x;
    const int h  = blockIdx.y;
    const int b  = blockIdx.z;
    const int bh = b * Hn + h;
    const int q0 = qb * 128;

    const float lam = __ldg(lam_p);
    const float scale = 0.125f;

    const int r0 = wm * 16 + gq;        // local Q row (fragment row)
    const int qrow = q0 + r0;           // global Q row

    // Q-lo tile -> smem (128 rows x 32 words)
    {
        const __nv_bfloat16* Qlg = g_Ql + ((size_t)bh * 2048 + q0) * 64;
#pragma unroll
        for (int i = 0; i < 4; i++) {
            int u = tid + i * 256;
            int row = u >> 3;
            int c4 = u & 7;
            int w = (4 * c4) ^ ((row & 7) << 2);
            *(uint4*)&sQl[row * 32 + w] = ((const uint4*)(Qlg + (size_t)row * 64))[c4];
        }
    }

    // Q-hi fragments -> registers (per warp: rows r0, r0+8; 4 k-steps)
    uint32_t qh[4][4];
    {
        const uint32_t* Q32 = (const uint32_t*)g_Qh;
        size_t base0 = ((size_t)bh * 2048 + qrow) * 32;
        size_t base1 = base0 + 8 * 32;
#pragma unroll
        for (int kt = 0; kt < 4; kt++) {
            qh[kt][0] = Q32[base0 + 8 * kt + tq];
            qh[kt][1] = Q32[base1 + 8 * kt + tq];
            qh[kt][2] = Q32[base0 + 8 * kt + 4 + tq];
            qh[kt][3] = Q32[base1 + 8 * kt + 4 + tq];
        }
    }

    float m_i[2] = {-1e30f, -1e30f};
    float l_i[2] = {0.f, 0.f};
    float o[8][4];
#pragma unroll
    for (int nt = 0; nt < 8; nt++)
#pragma unroll
        for (int e = 0; e < 4; e++) o[nt][e] = 0.f;

    const float* Bgb = Bg + (size_t)b * Nseq * Nseq;

    for (int kb = 0; kb < 32; kb++) {
        __syncthreads();
        // Load K tile (64 rows x 64 cols, hi+lo) and Vt tile (64 d-rows x 64 n-cols)
        {
            int row = tid >> 2;
            int qq = tid & 3;
            int w0 = (4 * qq) ^ ((row & 7) << 2);
            int w1 = (4 * qq + 16) ^ ((row & 7) << 2);
            const uint4* Khg = (const uint4*)(g_Kh + ((size_t)bh * 2048 + kb * 64 + row) * 64);
            const uint4* Klg = (const uint4*)(g_Kl + ((size_t)bh * 2048 + kb * 64 + row) * 64);
            *(uint4*)&sKh[row * 32 + w0] = Khg[qq];
            *(uint4*)&sKh[row * 32 + w1] = Khg[qq + 4];
            *(uint4*)&sKl[row * 32 + w0] = Klg[qq];
            *(uint4*)&sKl[row * 32 + w1] = Klg[qq + 4];
            const uint4* Vhg = (const uint4*)(g_Vth + ((size_t)bh * 64 + row) * 2048 + kb * 64);
            const uint4* Vlg = (const uint4*)(g_Vtl + ((size_t)bh * 64 + row) * 2048 + kb * 64);
            *(uint4*)&sVh[row * 32 + w0] = Vhg[qq];
            *(uint4*)&sVh[row * 32 + w1] = Vhg[qq + 4];
            *(uint4*)&sVl[row * 32 + w0] = Vlg[qq];
            *(uint4*)&sVl[row * 32 + w1] = Vlg[qq + 4];
        }
        __syncthreads();

        // S = Q K^T  (8 n-tiles of 8 cols, 4 k-steps over d)
        float s[8][4];
#pragma unroll
        for (int nt = 0; nt < 8; nt++)
#pragma unroll
            for (int e = 0; e < 4; e++) s[nt][e] = 0.f;

#pragma unroll
        for (int kt = 0; kt < 4; kt++) {
            uint32_t al[4];
            al[0] = sQl[QSW(r0,     8 * kt + tq)];
            al[1] = sQl[QSW(r0 + 8, 8 * kt + tq)];
            al[2] = sQl[QSW(r0,     8 * kt + 4 + tq)];
            al[3] = sQl[QSW(r0 + 8, 8 * kt + 4 + tq)];
#pragma unroll
            for (int nt = 0; nt < 8; nt++) {
                int kr = 8 * nt + gq;
                uint32_t kh[2], kl[2];
                kh[0] = sKh[QSW(kr, 8 * kt + tq)];
                kh[1] = sKh[QSW(kr, 8 * kt + 4 + tq)];
                kl[0] = sKl[QSW(kr, 8 * kt + tq)];
                kl[1] = sKl[QSW(kr, 8 * kt + 4 + tq)];
                mma_bf16(s[nt], qh[kt], kh);
                mma_bf16(s[nt], qh[kt], kl);
                mma_bf16(s[nt], al, kh);
            }
        }

        // scale + Gaussian bias
#pragma unroll
        for (int nt = 0; nt < 8; nt++) {
#pragma unroll
            for (int half = 0; half < 2; half++) {
                int row = qrow + half * 8;
                float2 bg = *(const float2*)(Bgb + (size_t)row * 2048 +
                                             kb * 64 + nt * 8 + tq * 2);
                s[nt][half * 2 + 0] = s[nt][half * 2 + 0] * scale + lam * bg.x;
                s[nt][half * 2 + 1] = s[nt][half * 2 + 1] * scale + lam * bg.y;
            }
        }

        // online softmax (row lives in a lane-quad)
#pragma unroll
        for (int half = 0; half < 2; half++) {
            float mx = -1e30f;
#pragma unroll
            for (int nt = 0; nt < 8; nt++)
                mx = fmaxf(mx, fmaxf(s[nt][half * 2], s[nt][half * 2 + 1]));
            mx = fmaxf(mx, __shfl_xor_sync(0xffffffffu, mx, 1));
            mx = fmaxf(mx, __shfl_xor_sync(0xffffffffu, mx, 2));
            float mn = fmaxf(m_i[half], mx);
            float corr = __expf(m_i[half] - mn);
            m_i[half] = mn;
            float rs = 0.f;
#pragma unroll
            for (int nt = 0; nt < 8; nt++) {
                s[nt][half * 2]     = __expf(s[nt][half * 2] - mn);
                s[nt][half * 2 + 1] = __expf(s[nt][half * 2 + 1] - mn);
                rs += s[nt][half * 2] + s[nt][half * 2 + 1];
            }
            rs += __shfl_xor_sync(0xffffffffu, rs, 1);
            rs += __shfl_xor_sync(0xffffffffu, rs, 2);
            l_i[half] = l_i[half] * corr + rs;
#pragma unroll
            for (int nt = 0; nt < 8; nt++) {
                o[nt][half * 2]     *= corr;
                o[nt][half * 2 + 1] *= corr;
            }
        }

        // O += P V  (P from registers; 4 k-steps over j, 8 n-tiles over d)
#pragma unroll
        for (int kt = 0; kt < 4; kt++) {
            float h0, l0, h1, l1, h2, l2, h3, l3;
            uint32_t ph[4], pl[4];
            split1(s[2 * kt][0], h0, l0); split1(s[2 * kt][1], h1, l1);
            split1(s[2 * kt][2], h2, l2); split1(s[2 * kt][3], h3, l3);
            ph[0] = pack2(h0, h1); pl[0] = pack2(l0, l1);
            ph[1] = pack2(h2, h3); pl[1] = pack2(l2, l3);
            split1(s[2 * kt + 1][0], h0, l0); split1(s[2 * kt + 1][1], h1, l1);
            split1(s[2 * kt + 1][2], h2, l2); split1(s[2 * kt + 1][3], h3, l3);
            ph[2] = pack2(h0, h1); pl[2] = pack2(l0, l1);
            ph[3] = pack2(h2, h3); pl[3] = pack2(l2, l3);
#pragma unroll
            for (int nt = 0; nt < 8; nt++) {
                int vr = 8 * nt + gq;
                uint32_t vh[2], vl[2];
                vh[0] = sVh[QSW(vr, 8 * kt + tq)];
                vh[1] = sVh[QSW(vr, 8 * kt + 4 + tq)];
                vl[0] = sVl[QSW(vr, 8 * kt + tq)];
                vl[1] = sVl[QSW(vr, 8 * kt + 4 + tq)];
                mma_bf16(o[nt], ph, vh);
                mma_bf16(o[nt], ph, vl);
                mma_bf16(o[nt], pl, vh);
            }
        }
    }

    // Epilogue: normalize, split hi/lo, write to g_oh/g_ol [b][n][1024]
    float inv0 = 1.0f / l_i[0];
    float inv1 = 1.0f / l_i[1];
#pragma unroll
    for (int nt = 0; nt < 8; nt++) {
#pragma unroll
        for (int half = 0; half < 2; half++) {
            float inv = half ? inv1 : inv0;
            int row = qrow + half * 8;
            float v0 = o[nt][half * 2 + 0] * inv;
            float v1 = o[nt][half * 2 + 1] * inv;
            float h0, l0, h1, l1;
            split1(v0, h0, l0);
            split1(v1, h1, l1);
            size_t ui = ((size_t)(b * 2048) + row) * 512 + h * 32 + nt * 4 + tq;
            ((uint32_t*)g_oh)[ui] = pack2(h0, h1);
            ((uint32_t*)g_ol)[ui] = pack2(l0, l1);
        }
    }
}

// ---------------------------------------------------------------------------
extern "C" void kernel_launch(void* const* d_in, const int* in_sizes, int n_in,
                              void* d_out, int out_size)
{
    const float* x   = (const float*)d_in[0];
    const float* Bg  = (const float*)d_in[1];
    const float* Wq  = (const float*)d_in[2];
    const float* bq  = (const float*)d_in[3];
    const float* Wk  = (const float*)d_in[4];
    const float* bk  = (const float*)d_in[5];
    const float* Wv  = (const float*)d_in[6];
    const float* bv  = (const float*)d_in[7];
    const float* Wo  = (const float*)d_in[8];
    const float* bo  = (const float*)d_in[9];
    const float* lam = (const float*)d_in[10];
    float* out = (float*)d_out;

    conv_split_x<<<4096, 256>>>((const float4*)x);
    conv_w<<<dim3(32, 32, 4), dim3(32, 8)>>>(Wq, Wk, Wv, Wo);

    mma_qkv<<<dim3(8, 32, 3), 256>>>(bq, bk, bv);
    transpose_v<<<dim3(64, 2, 32), dim3(32, 8)>>>();

    attn_mma<<<dim3(16, 16, 2), 256>>>(Bg, lam);

    mma_out<<<dim3(8, 32, 1), 256>>>(bo, out);
}

// round 6
// speedup vs baseline: 2.5957x; 1.1805x over previous
#include <cuda_runtime.h>
#include <cuda_bf16.h>
#include <cstdint>
#include <math.h>

// Problem constants
#define Bdim 2
#define Nseq 2048
#define Dmod 1024
#define Hn   16
#define HD   64

// ---------------------------------------------------------------------------
// Scratch (alloc-free rule: __device__ globals)
// ---------------------------------------------------------------------------
#define QKV_ELEMS ((size_t)Bdim * Hn * Nseq * HD)
__device__ __nv_bfloat16 g_Qh[QKV_ELEMS], g_Ql[QKV_ELEMS];   // [b][h][n][d]
__device__ __nv_bfloat16 g_Kh[QKV_ELEMS], g_Kl[QKV_ELEMS];
__device__ __nv_bfloat16 g_Vh[QKV_ELEMS], g_Vl[QKV_ELEMS];
__device__ __nv_bfloat16 g_Vth[QKV_ELEMS], g_Vtl[QKV_ELEMS]; // [b][h][d][n]

__device__ __nv_bfloat16 g_xh[(size_t)4096 * 1024];
__device__ __nv_bfloat16 g_xl[(size_t)4096 * 1024];
__device__ __nv_bfloat16 g_oh[(size_t)4096 * 1024];          // attn out [b][n][1024]
__device__ __nv_bfloat16 g_ol[(size_t)4096 * 1024];
__device__ __nv_bfloat16 g_wth[4][(size_t)1024 * 1024];      // W^T [n][k]
__device__ __nv_bfloat16 g_wtl[4][(size_t)1024 * 1024];

// ---------------------------------------------------------------------------
// PTX helpers
// ---------------------------------------------------------------------------
__device__ __forceinline__ void mma_bf16(float (&d)[4],
                                         const uint32_t (&a)[4],
                                         const uint32_t (&b)[2])
{
    asm volatile(
        "mma.sync.aligned.m16n8k16.row.col.f32.bf16.bf16.f32 "
        "{%0,%1,%2,%3}, {%4,%5,%6,%7}, {%8,%9}, {%0,%1,%2,%3};"
        : "+f"(d[0]), "+f"(d[1]), "+f"(d[2]), "+f"(d[3])
        : "r"(a[0]), "r"(a[1]), "r"(a[2]), "r"(a[3]),
          "r"(b[0]), "r"(b[1]));
}

__device__ __forceinline__ void ldsm_x4(uint32_t (&r)[4], uint32_t addr)
{
    asm volatile("ldmatrix.sync.aligned.m8n8.x4.shared.b16 {%0,%1,%2,%3}, [%4];"
                 : "=r"(r[0]), "=r"(r[1]), "=r"(r[2]), "=r"(r[3]) : "r"(addr));
}

__device__ __forceinline__ uint32_t smem_to_u32(const void* p) {
    uint32_t a;
    asm("{ .reg .u64 t; cvta.to.shared.u64 t, %1; cvt.u32.u64 %0, t; }"
        : "=r"(a) : "l"(p));
    return a;
}

#define CP_ASYNC16(saddr, gptr) \
    asm volatile("cp.async.cg.shared.global [%0], [%1], 16;" \
                 :: "r"(saddr), "l"(gptr) : "memory")
#define CP_COMMIT() asm volatile("cp.async.commit_group;" ::: "memory")
#define CP_WAIT1()  asm volatile("cp.async.wait_group 1;" ::: "memory")
#define CP_WAIT0()  asm volatile("cp.async.wait_group 0;" ::: "memory")

__device__ __forceinline__ uint32_t pack2(float a, float b)
{
    return (uint32_t)__bfloat16_as_ushort(__float2bfloat16_rn(a)) |
           ((uint32_t)__bfloat16_as_ushort(__float2bfloat16_rn(b)) << 16);
}

__device__ __forceinline__ void split1(float v, float& hf, float& lf)
{
    __nv_bfloat16 h = __float2bfloat16_rn(v);
    hf = __bfloat162float(h);
    lf = v - hf;
}

// ---------------------------------------------------------------------------
// Conversions
// ---------------------------------------------------------------------------
__device__ __forceinline__ void split4(float4 v, ushort4& H, ushort4& L)
{
    __nv_bfloat16 h0 = __float2bfloat16_rn(v.x);
    __nv_bfloat16 h1 = __float2bfloat16_rn(v.y);
    __nv_bfloat16 h2 = __float2bfloat16_rn(v.z);
    __nv_bfloat16 h3 = __float2bfloat16_rn(v.w);
    H = {__bfloat16_as_ushort(h0), __bfloat16_as_ushort(h1),
         __bfloat16_as_ushort(h2), __bfloat16_as_ushort(h3)};
    L = {__bfloat16_as_ushort(__float2bfloat16_rn(v.x - __bfloat162float(h0))),
         __bfloat16_as_ushort(__float2bfloat16_rn(v.y - __bfloat162float(h1))),
         __bfloat16_as_ushort(__float2bfloat16_rn(v.z - __bfloat162float(h2))),
         __bfloat16_as_ushort(__float2bfloat16_rn(v.w - __bfloat162float(h3)))};
}

__global__ void conv_split_x(const float4* __restrict__ src)
{
    int i = blockIdx.x * 256 + threadIdx.x;
    ushort4 H, L;
    split4(src[i], H, L);
    ((ushort4*)g_xh)[i] = H;
    ((ushort4*)g_xl)[i] = L;
}

__global__ void conv_w(const float* __restrict__ Wq, const float* __restrict__ Wk,
                       const float* __restrict__ Wv, const float* __restrict__ Wo)
{
    __shared__ float t[32][33];
    int z = blockIdx.z;
    const float* W = (z == 0) ? Wq : (z == 1) ? Wk : (z == 2) ? Wv : Wo;
    int n0 = blockIdx.x * 32, k0 = blockIdx.y * 32;
    int tx = threadIdx.x, ty = threadIdx.y;
#pragma unroll
    for (int j = 0; j < 32; j += 8)
        t[ty + j][tx] = W[(size_t)(k0 + ty + j) * 1024 + n0 + tx];
    __syncthreads();
#pragma unroll
    for (int j = 0; j < 32; j += 8) {
        float v = t[tx][ty + j];
        __nv_bfloat16 h = __float2bfloat16_rn(v);
        __nv_bfloat16 l = __float2bfloat16_rn(v - __bfloat162float(h));
        size_t idx = (size_t)(n0 + ty + j) * 1024 + k0 + tx;
        g_wth[z][idx] = h;
        g_wtl[z][idx] = l;
    }
}

// V [bh][n][d] -> Vt [bh][d][n], hi+lo
__global__ void transpose_v()
{
    __shared__ __nv_bfloat16 th[32][33], tl[32][33];
    int bh = blockIdx.z;
    int n0 = blockIdx.x * 32, d0 = blockIdx.y * 32;
    int tx = threadIdx.x, ty = threadIdx.y;
#pragma unroll
    for (int j = 0; j < 32; j += 8) {
        size_t src = ((size_t)bh * 2048 + n0 + ty + j) * 64 + d0 + tx;
        th[ty + j][tx] = g_Vh[src];
        tl[ty + j][tx] = g_Vl[src];
    }
    __syncthreads();
#pragma unroll
    for (int j = 0; j < 32; j += 8) {
        size_t dst = ((size_t)bh * 64 + d0 + ty + j) * 2048 + n0 + tx;
        g_Vth[dst] = th[tx][ty + j];
        g_Vtl[dst] = tl[tx][ty + j];
    }
}

// ---------------------------------------------------------------------------
// HMMA bf16x3 GEMM with ldmatrix fragment loads.
// C[4096,1024] = A @ B^T + bias (B stored [n][k]).
// ---------------------------------------------------------------------------
#define TSTRIDE 20

template <bool HEAD>
__device__ __forceinline__ void mma_gemm_body(const __nv_bfloat16* __restrict__ Ahi,
                                              const __nv_bfloat16* __restrict__ Alo,
                                              const __nv_bfloat16* __restrict__ Bhi,
                                              const __nv_bfloat16* __restrict__ Blo,
                                              const float* __restrict__ bias,
                                              float* __restrict__ out,
                                              __nv_bfloat16* __restrict__ outH,
                                              __nv_bfloat16* __restrict__ outL)
{
    __shared__ uint32_t Ah[128 * TSTRIDE];
    __shared__ uint32_t Al[128 * TSTRIDE];
    __shared__ uint32_t Bh[128 * TSTRIDE];
    __shared__ uint32_t Bl[128 * TSTRIDE];

    const int tid = threadIdx.x;
    const int wid = tid >> 5;
    const int lid = tid & 31;
    const int wm  = wid & 3;
    const int wn  = wid >> 2;
    const int gq  = lid >> 2;
    const int tq  = lid & 3;
    const int m0 = blockIdx.y * 128;
    const int n0 = blockIdx.x * 128;

    const uint32_t uAh = smem_to_u32(Ah);
    const uint32_t uAl = smem_to_u32(Al);
    const uint32_t uBh = smem_to_u32(Bh);
    const uint32_t uBl = smem_to_u32(Bl);

    // ldmatrix lane geometry
    const int lt  = lid >> 3;   // tile id 0..3
    const int lr  = lid & 7;    // row within tile

    float acc[2][8][4];
#pragma unroll
    for (int mt = 0; mt < 2; mt++)
#pragma unroll
        for (int nt = 0; nt < 8; nt++)
#pragma unroll
            for (int e = 0; e < 4; e++) acc[mt][nt][e] = 0.f;

    for (int kt = 0; kt < 1024; kt += 32) {
#pragma unroll
        for (int q = 0; q < 2; q++) {
            int u = tid * 2 + q;
            int row = u >> 2;
            int c4 = u & 3;
            size_t ga = (size_t)(m0 + row) * 1024 + kt;
            size_t gb = (size_t)(n0 + row) * 1024 + kt;
            *(uint4*)&Ah[row * TSTRIDE + c4 * 4] = ((const uint4*)(Ahi + ga))[c4];
            *(uint4*)&Al[row * TSTRIDE + c4 * 4] = ((const uint4*)(Alo + ga))[c4];
            *(uint4*)&Bh[row * TSTRIDE + c4 * 4] = ((const uint4*)(Bhi + gb))[c4];
            *(uint4*)&Bl[row * TSTRIDE + c4 * 4] = ((const uint4*)(Blo + gb))[c4];
        }
        __syncthreads();

#pragma unroll
        for (int ks = 0; ks < 2; ks++) {
            const int c0 = ks * 8;
            // B fragments via ldmatrix: tiles (rowb, c0),(rowb,c0+4),(rowb+8,c0),(rowb+8,c0+4)
            uint32_t bh[8][2], bl[8][2];
#pragma unroll
            for (int a = 0; a < 4; a++) {
                int row = wn * 64 + 16 * a + 8 * (lt >> 1) + lr;
                int col = c0 + 4 * (lt & 1);
                uint32_t off = (uint32_t)(row * TSTRIDE + col) * 4;
                uint32_t f[4];
                ldsm_x4(f, uBh + off);
                bh[2 * a][0] = f[0]; bh[2 * a][1] = f[1];
                bh[2 * a + 1][0] = f[2]; bh[2 * a + 1][1] = f[3];
                ldsm_x4(f, uBl + off);
                bl[2 * a][0] = f[0]; bl[2 * a][1] = f[1];
                bl[2 * a + 1][0] = f[2]; bl[2 * a + 1][1] = f[3];
            }
#pragma unroll
            for (int mt = 0; mt < 2; mt++) {
                // A fragments: tiles (rows0,c0),(rows+8,c0),(rows0,c0+4),(rows+8,c0+4)
                int row = wm * 32 + 16 * mt + 8 * (lt & 1) + lr;
                int col = c0 + 4 * (lt >> 1);
                uint32_t off = (uint32_t)(row * TSTRIDE + col) * 4;
                uint32_t ah[4], al[4];
                ldsm_x4(ah, uAh + off);
                ldsm_x4(al, uAl + off);
#pragma unroll
                for (int nt = 0; nt < 8; nt++) {
                    mma_bf16(acc[mt][nt], ah, bh[nt]);
                    mma_bf16(acc[mt][nt], ah, bl[nt]);
                    mma_bf16(acc[mt][nt], al, bh[nt]);
                }
            }
        }
        __syncthreads();
    }

#pragma unroll
    for (int mt = 0; mt < 2; mt++) {
#pragma unroll
        for (int nt = 0; nt < 8; nt++) {
            int R = m0 + wm * 32 + mt * 16 + gq;
            int C = n0 + wn * 64 + nt * 8 + tq * 2;
            float b0 = bias[C], b1 = bias[C + 1];
#pragma unroll
            for (int half = 0; half < 2; half++) {
                int r = R + half * 8;
                float v0 = acc[mt][nt][half * 2 + 0] + b0;
                float v1 = acc[mt][nt][half * 2 + 1] + b1;
                if (HEAD) {
                    int b = r >> 11;
                    int n = r & 2047;
                    int hh = C >> 6;
                    int d = C & 63;
                    float h0, l0, h1, l1;
                    split1(v0, h0, l0);
                    split1(v1, h1, l1);
                    size_t ui = (((size_t)(b * Hn + hh)) * 2048 + n) * 32 + (d >> 1);
                    ((uint32_t*)outH)[ui] = pack2(h0, h1);
                    ((uint32_t*)outL)[ui] = pack2(l0, l1);
                } else {
                    *(float2*)(out + (size_t)r * 1024 + C) = make_float2(v0, v1);
                }
            }
        }
    }
}

__global__ void __launch_bounds__(256, 2)
mma_qkv(const float* __restrict__ bq, const float* __restrict__ bk,
        const float* __restrict__ bv)
{
    int z = blockIdx.z;
    const float* bias = (z == 0) ? bq : (z == 1) ? bk : bv;
    __nv_bfloat16* oh = (z == 0) ? g_Qh : (z == 1) ? g_Kh : g_Vh;
    __nv_bfloat16* ol = (z == 0) ? g_Ql : (z == 1) ? g_Kl : g_Vl;
    mma_gemm_body<true>(g_xh, g_xl, g_wth[z], g_wtl[z], bias, nullptr, oh, ol);
}

__global__ void __launch_bounds__(256, 2)
mma_out(const float* __restrict__ bo, float* __restrict__ out)
{
    mma_gemm_body<false>(g_oh, g_ol, g_wth[3], g_wtl[3], bo, out, nullptr, nullptr);
}

// ---------------------------------------------------------------------------
// HMMA flash attention v3: ldmatrix fragments + cp.async double buffering.
// BQ=128, BK=64, 8 warps. Dynamic smem 80KB:
//   [0,16K)   Q-lo (128x32 words, XOR swizzle)
//   [16K+bi*32K) buffers: Kh(8K) Kl(8K) Vh(8K) Vl(8K)
// ---------------------------------------------------------------------------
#define QSW(r, w) (((r) * 32) + ((w) ^ (((r) & 7) << 2)))
#define ATT_SMEM (16384 + 2 * 32768)

__global__ void __launch_bounds__(256, 2)
attn_mma(const float* __restrict__ Bg, const float* __restrict__ lam_p)
{
    extern __shared__ char smem[];
    const uint32_t sb = smem_to_u32(smem);

    const int tid = threadIdx.x;
    const int wm  = tid >> 5;
    const int lid = tid & 31;
    const int gq  = lid >> 2;
    const int tq  = lid & 3;
    const int lt  = lid >> 3;
    const int lr  = lid & 7;
    const int qb = blockIdx.x;
    const int h  = blockIdx.y;
    const int b  = blockIdx.z;
    const int bh = b * Hn + h;
    const int q0 = qb * 128;

    const float lam = __ldg(lam_p);
    const float scale = 0.125f;

    const int r0 = wm * 16 + gq;
    const int qrow = q0 + r0;

    // cp.async loader for K/V tiles of block kb into buffer bi
    const int ldrow = tid >> 2;
    const int ldq   = tid & 3;
    const uint32_t lw0 = (uint32_t)((4 * ldq) ^ ((ldrow & 7) << 2)) * 4;
    const uint32_t lw1 = (uint32_t)((4 * ldq + 16) ^ ((ldrow & 7) << 2)) * 4;
    const uint32_t lrow128 = (uint32_t)ldrow * 128;

#define LOAD_KB(kb, bi) do { \
        uint32_t bufb = sb + 16384 + (bi) * 32768; \
        const char* pKh = (const char*)(g_Kh + ((size_t)bh * 2048 + (kb) * 64 + ldrow) * 64); \
        const char* pKl = (const char*)(g_Kl + ((size_t)bh * 2048 + (kb) * 64 + ldrow) * 64); \
        const char* pVh = (const char*)(g_Vth + ((size_t)bh * 64 + ldrow) * 2048 + (kb) * 64); \
        const char* pVl = (const char*)(g_Vtl + ((size_t)bh * 64 + ldrow) * 2048 + (kb) * 64); \
        CP_ASYNC16(bufb + lrow128 + lw0, pKh + ldq * 16); \
        CP_ASYNC16(bufb + lrow128 + lw1, pKh + 64 + ldq * 16); \
        CP_ASYNC16(bufb + 8192 + lrow128 + lw0, pKl + ldq * 16); \
        CP_ASYNC16(bufb + 8192 + lrow128 + lw1, pKl + 64 + ldq * 16); \
        CP_ASYNC16(bufb + 16384 + lrow128 + lw0, pVh + ldq * 16); \
        CP_ASYNC16(bufb + 16384 + lrow128 + lw1, pVh + 64 + ldq * 16); \
        CP_ASYNC16(bufb + 24576 + lrow128 + lw0, pVl + ldq * 16); \
        CP_ASYNC16(bufb + 24576 + lrow128 + lw1, pVl + 64 + ldq * 16); \
        CP_COMMIT(); \
    } while (0)

    // Q-lo tile -> smem
    {
        const __nv_bfloat16* Qlg = g_Ql + ((size_t)bh * 2048 + q0) * 64;
#pragma unroll
        for (int i = 0; i < 4; i++) {
            int u = tid + i * 256;
            int row = u >> 3;
            int c4 = u & 7;
            int w = (4 * c4) ^ ((row & 7) << 2);
            *(uint4*)(smem + (row * 32 + w) * 4) = ((const uint4*)(Qlg + (size_t)row * 64))[c4];
        }
    }

    // Q-hi fragments -> registers
    uint32_t qh[4][4];
    {
        const uint32_t* Q32 = (const uint32_t*)g_Qh;
        size_t base0 = ((size_t)bh * 2048 + qrow) * 32;
        size_t base1 = base0 + 8 * 32;
#pragma unroll
        for (int kt = 0; kt < 4; kt++) {
            qh[kt][0] = Q32[base0 + 8 * kt + tq];
            qh[kt][1] = Q32[base1 + 8 * kt + tq];
            qh[kt][2] = Q32[base0 + 8 * kt + 4 + tq];
            qh[kt][3] = Q32[base1 + 8 * kt + 4 + tq];
        }
    }

    // Prologue: prefetch kb=0,1
    LOAD_KB(0, 0);
    LOAD_KB(1, 1);

    float m_i[2] = {-1e30f, -1e30f};
    float l_i[2] = {0.f, 0.f};
    float o[8][4];
#pragma unroll
    for (int nt = 0; nt < 8; nt++)
#pragma unroll
        for (int e = 0; e < 4; e++) o[nt][e] = 0.f;

    const float* Bgb = Bg + (size_t)b * Nseq * Nseq;

    // lane addresses for fragment ldmatrix (row/col geometry)
    // K/V tiles: per (a, kt): row = 16a + 8*(lt>>1) + lr, wb = 8kt + 4*(lt&1)
    // Q-lo:      per kt:     row = wm*16 + 8*(lt&1) + lr, wb = 8kt + 4*(lt>>1)

    for (int kb = 0; kb < 32; kb++) {
        if (kb == 31) { CP_WAIT0(); } else { CP_WAIT1(); }
        __syncthreads();

        const uint32_t bufb = sb + 16384 + (kb & 1) * 32768;
        const uint32_t uKh = bufb;
        const uint32_t uKl = bufb + 8192;
        const uint32_t uVh = bufb + 16384;
        const uint32_t uVl = bufb + 24576;

        // S = Q K^T
        float s[8][4];
#pragma unroll
        for (int nt = 0; nt < 8; nt++)
#pragma unroll
            for (int e = 0; e < 4; e++) s[nt][e] = 0.f;

#pragma unroll
        for (int kt = 0; kt < 4; kt++) {
            uint32_t al[4];
            {
                int row = wm * 16 + 8 * (lt & 1) + lr;
                int wb = 8 * kt + 4 * (lt >> 1);
                ldsm_x4(al, sb + (uint32_t)QSW(row, wb) * 4);
            }
#pragma unroll
            for (int a = 0; a < 4; a++) {
                int row = 16 * a + 8 * (lt >> 1) + lr;
                int wb = 8 * kt + 4 * (lt & 1);
                uint32_t off = (uint32_t)QSW(row, wb) * 4;
                uint32_t kh4[4], kl4[4];
                ldsm_x4(kh4, uKh + off);
                ldsm_x4(kl4, uKl + off);
                uint32_t kh0[2] = {kh4[0], kh4[1]}, kh1[2] = {kh4[2], kh4[3]};
                uint32_t kl0[2] = {kl4[0], kl4[1]}, kl1[2] = {kl4[2], kl4[3]};
                mma_bf16(s[2 * a], qh[kt], kh0);
                mma_bf16(s[2 * a], qh[kt], kl0);
                mma_bf16(s[2 * a], al, kh0);
                mma_bf16(s[2 * a + 1], qh[kt], kh1);
                mma_bf16(s[2 * a + 1], qh[kt], kl1);
                mma_bf16(s[2 * a + 1], al, kh1);
            }
        }

        // scale + Gaussian bias
#pragma unroll
        for (int nt = 0; nt < 8; nt++) {
#pragma unroll
            for (int half = 0; half < 2; half++) {
                int row = qrow + half * 8;
                float2 bg = *(const float2*)(Bgb + (size_t)row * 2048 +
                                             kb * 64 + nt * 8 + tq * 2);
                s[nt][half * 2 + 0] = s[nt][half * 2 + 0] * scale + lam * bg.x;
                s[nt][half * 2 + 1] = s[nt][half * 2 + 1] * scale + lam * bg.y;
            }
        }

        // online softmax
#pragma unroll
        for (int half = 0; half < 2; half++) {
            float mx = -1e30f;
#pragma unroll
            for (int nt = 0; nt < 8; nt++)
                mx = fmaxf(mx, fmaxf(s[nt][half * 2], s[nt][half * 2 + 1]));
            mx = fmaxf(mx, __shfl_xor_sync(0xffffffffu, mx, 1));
            mx = fmaxf(mx, __shfl_xor_sync(0xffffffffu, mx, 2));
            float mn = fmaxf(m_i[half], mx);
            float corr = __expf(m_i[half] - mn);
            m_i[half] = mn;
            float rs = 0.f;
#pragma unroll
            for (int nt = 0; nt < 8; nt++) {
                s[nt][half * 2]     = __expf(s[nt][half * 2] - mn);
                s[nt][half * 2 + 1] = __expf(s[nt][half * 2 + 1] - mn);
                rs += s[nt][half * 2] + s[nt][half * 2 + 1];
            }
            rs += __shfl_xor_sync(0xffffffffu, rs, 1);
            rs += __shfl_xor_sync(0xffffffffu, rs, 2);
            l_i[half] = l_i[half] * corr + rs;
#pragma unroll
            for (int nt = 0; nt < 8; nt++) {
                o[nt][half * 2]     *= corr;
                o[nt][half * 2 + 1] *= corr;
            }
        }

        // O += P V
#pragma unroll
        for (int kt = 0; kt < 4; kt++) {
            float h0, l0, h1, l1, h2, l2, h3, l3;
            uint32_t ph[4], pl[4];
            split1(s[2 * kt][0], h0, l0); split1(s[2 * kt][1], h1, l1);
            split1(s[2 * kt][2], h2, l2); split1(s[2 * kt][3], h3, l3);
            ph[0] = pack2(h0, h1); pl[0] = pack2(l0, l1);
            ph[1] = pack2(h2, h3); pl[1] = pack2(l2, l3);
            split1(s[2 * kt + 1][0], h0, l0); split1(s[2 * kt + 1][1], h1, l1);
            split1(s[2 * kt + 1][2], h2, l2); split1(s[2 * kt + 1][3], h3, l3);
            ph[2] = pack2(h0, h1); pl[2] = pack2(l0, l1);
            ph[3] = pack2(h2, h3); pl[3] = pack2(l2, l3);
#pragma unroll
            for (int a = 0; a < 4; a++) {
                int row = 16 * a + 8 * (lt >> 1) + lr;
                int wb = 8 * kt + 4 * (lt & 1);
                uint32_t off = (uint32_t)QSW(row, wb) * 4;
                uint32_t vh4[4], vl4[4];
                ldsm_x4(vh4, uVh + off);
                ldsm_x4(vl4, uVl + off);
                uint32_t vh0[2] = {vh4[0], vh4[1]}, vh1[2] = {vh4[2], vh4[3]};
                uint32_t vl0[2] = {vl4[0], vl4[1]}, vl1[2] = {vl4[2], vl4[3]};
                mma_bf16(o[2 * a], ph, vh0);
                mma_bf16(o[2 * a], ph, vl0);
                mma_bf16(o[2 * a], pl, vh0);
                mma_bf16(o[2 * a + 1], ph, vh1);
                mma_bf16(o[2 * a + 1], ph, vl1);
                mma_bf16(o[2 * a + 1], pl, vh1);
            }
        }

        __syncthreads();
        if (kb + 2 < 32) LOAD_KB(kb + 2, kb & 1);
    }

    // Epilogue
    float inv0 = 1.0f / l_i[0];
    float inv1 = 1.0f / l_i[1];
#pragma unroll
    for (int nt = 0; nt < 8; nt++) {
#pragma unroll
        for (int half = 0; half < 2; half++) {
            float inv = half ? inv1 : inv0;
            int row = qrow + half * 8;
            float v0 = o[nt][half * 2 + 0] * inv;
            float v1 = o[nt][half * 2 + 1] * inv;
            float h0, l0, h1, l1;
            split1(v0, h0, l0);
            split1(v1, h1, l1);
            size_t ui = ((size_t)(b * 2048) + row) * 512 + h * 32 + nt * 4 + tq;
            ((uint32_t*)g_oh)[ui] = pack2(h0, h1);
            ((uint32_t*)g_ol)[ui] = pack2(l0, l1);
        }
    }
}

// ---------------------------------------------------------------------------
extern "C" void kernel_launch(void* const* d_in, const int* in_sizes, int n_in,
                              void* d_out, int out_size)
{
    const float* x   = (const float*)d_in[0];
    const float* Bg  = (const float*)d_in[1];
    const float* Wq  = (const float*)d_in[2];
    const float* bq  = (const float*)d_in[3];
    const float* Wk  = (const float*)d_in[4];
    const float* bk  = (const float*)d_in[5];
    const float* Wv  = (const float*)d_in[6];
    const float* bv  = (const float*)d_in[7];
    const float* Wo  = (const float*)d_in[8];
    const float* bo  = (const float*)d_in[9];
    const float* lam = (const float*)d_in[10];
    float* out = (float*)d_out;

    cudaFuncSetAttribute(attn_mma, cudaFuncAttributeMaxDynamicSharedMemorySize, ATT_SMEM);

    conv_split_x<<<4096, 256>>>((const float4*)x);
    conv_w<<<dim3(32, 32, 4), dim3(32, 8)>>>(Wq, Wk, Wv, Wo);

    mma_qkv<<<dim3(8, 32, 3), 256>>>(bq, bk, bv);
    transpose_v<<<dim3(64, 2, 32), dim3(32, 8)>>>();

    attn_mma<<<dim3(16, 16, 2), 256, ATT_SMEM>>>(Bg, lam);

    mma_out<<<dim3(8, 32, 1), 256>>>(bo, out);
}

// round 7
// speedup vs baseline: 2.7038x; 1.0416x over previous
#include <cuda_runtime.h>
#include <cuda_bf16.h>
#include <cstdint>
#include <math.h>

// Problem constants
#define Bdim 2
#define Nseq 2048
#define Dmod 1024
#define Hn   16
#define HD   64

// ---------------------------------------------------------------------------
// Scratch (alloc-free rule: __device__ globals)
// ---------------------------------------------------------------------------
#define QKV_ELEMS ((size_t)Bdim * Hn * Nseq * HD)
__device__ __nv_bfloat16 g_Qh[QKV_ELEMS], g_Ql[QKV_ELEMS];   // [b][h][n][d]
__device__ __nv_bfloat16 g_Kh[QKV_ELEMS], g_Kl[QKV_ELEMS];
__device__ __nv_bfloat16 g_Vh[QKV_ELEMS], g_Vl[QKV_ELEMS];
__device__ __nv_bfloat16 g_Vth[QKV_ELEMS], g_Vtl[QKV_ELEMS]; // [b][h][d][n]

__device__ __nv_bfloat16 g_xh[(size_t)4096 * 1024];
__device__ __nv_bfloat16 g_xl[(size_t)4096 * 1024];
__device__ __nv_bfloat16 g_oh[(size_t)4096 * 1024];          // attn out [b][n][1024]
__device__ __nv_bfloat16 g_ol[(size_t)4096 * 1024];
__device__ __nv_bfloat16 g_wth[4][(size_t)1024 * 1024];      // W^T [n][k]
__device__ __nv_bfloat16 g_wtl[4][(size_t)1024 * 1024];

// ---------------------------------------------------------------------------
// PTX helpers
// ---------------------------------------------------------------------------
__device__ __forceinline__ void mma_bf16(float (&d)[4],
                                         const uint32_t (&a)[4],
                                         const uint32_t (&b)[2])
{
    asm volatile(
        "mma.sync.aligned.m16n8k16.row.col.f32.bf16.bf16.f32 "
        "{%0,%1,%2,%3}, {%4,%5,%6,%7}, {%8,%9}, {%0,%1,%2,%3};"
        : "+f"(d[0]), "+f"(d[1]), "+f"(d[2]), "+f"(d[3])
        : "r"(a[0]), "r"(a[1]), "r"(a[2]), "r"(a[3]),
          "r"(b[0]), "r"(b[1]));
}

__device__ __forceinline__ void ldsm_x4(uint32_t (&r)[4], uint32_t addr)
{
    asm volatile("ldmatrix.sync.aligned.m8n8.x4.shared.b16 {%0,%1,%2,%3}, [%4];"
                 : "=r"(r[0]), "=r"(r[1]), "=r"(r[2]), "=r"(r[3]) : "r"(addr));
}

__device__ __forceinline__ uint32_t smem_to_u32(const void* p) {
    uint32_t a;
    asm("{ .reg .u64 t; cvta.to.shared.u64 t, %1; cvt.u32.u64 %0, t; }"
        : "=r"(a) : "l"(p));
    return a;
}

#define CP_ASYNC16(saddr, gptr) \
    asm volatile("cp.async.cg.shared.global [%0], [%1], 16;" \
                 :: "r"(saddr), "l"(gptr) : "memory")
#define CP_COMMIT() asm volatile("cp.async.commit_group;" ::: "memory")
#define CP_WAIT1()  asm volatile("cp.async.wait_group 1;" ::: "memory")
#define CP_WAIT0()  asm volatile("cp.async.wait_group 0;" ::: "memory")

__device__ __forceinline__ uint32_t pack2(float a, float b)
{
    return (uint32_t)__bfloat16_as_ushort(__float2bfloat16_rn(a)) |
           ((uint32_t)__bfloat16_as_ushort(__float2bfloat16_rn(b)) << 16);
}

__device__ __forceinline__ void split1(float v, float& hf, float& lf)
{
    __nv_bfloat16 h = __float2bfloat16_rn(v);
    hf = __bfloat162float(h);
    lf = v - hf;
}

// ---------------------------------------------------------------------------
// Conversions
// ---------------------------------------------------------------------------
__device__ __forceinline__ void split4(float4 v, ushort4& H, ushort4& L)
{
    __nv_bfloat16 h0 = __float2bfloat16_rn(v.x);
    __nv_bfloat16 h1 = __float2bfloat16_rn(v.y);
    __nv_bfloat16 h2 = __float2bfloat16_rn(v.z);
    __nv_bfloat16 h3 = __float2bfloat16_rn(v.w);
    H = {__bfloat16_as_ushort(h0), __bfloat16_as_ushort(h1),
         __bfloat16_as_ushort(h2), __bfloat16_as_ushort(h3)};
    L = {__bfloat16_as_ushort(__float2bfloat16_rn(v.x - __bfloat162float(h0))),
         __bfloat16_as_ushort(__float2bfloat16_rn(v.y - __bfloat162float(h1))),
         __bfloat16_as_ushort(__float2bfloat16_rn(v.z - __bfloat162float(h2))),
         __bfloat16_as_ushort(__float2bfloat16_rn(v.w - __bfloat162float(h3)))};
}

__global__ void conv_split_x(const float4* __restrict__ src)
{
    int i = blockIdx.x * 256 + threadIdx.x;
    ushort4 H, L;
    split4(src[i], H, L);
    ((ushort4*)g_xh)[i] = H;
    ((ushort4*)g_xl)[i] = L;
}

__global__ void conv_w(const float* __restrict__ Wq, const float* __restrict__ Wk,
                       const float* __restrict__ Wv, const float* __restrict__ Wo)
{
    __shared__ float t[32][33];
    int z = blockIdx.z;
    const float* W = (z == 0) ? Wq : (z == 1) ? Wk : (z == 2) ? Wv : Wo;
    int n0 = blockIdx.x * 32, k0 = blockIdx.y * 32;
    int tx = threadIdx.x, ty = threadIdx.y;
#pragma unroll
    for (int j = 0; j < 32; j += 8)
        t[ty + j][tx] = W[(size_t)(k0 + ty + j) * 1024 + n0 + tx];
    __syncthreads();
#pragma unroll
    for (int j = 0; j < 32; j += 8) {
        float v = t[tx][ty + j];
        __nv_bfloat16 h = __float2bfloat16_rn(v);
        __nv_bfloat16 l = __float2bfloat16_rn(v - __bfloat162float(h));
        size_t idx = (size_t)(n0 + ty + j) * 1024 + k0 + tx;
        g_wth[z][idx] = h;
        g_wtl[z][idx] = l;
    }
}

// V [bh][n][d] -> Vt [bh][d][n], hi+lo
__global__ void transpose_v()
{
    __shared__ __nv_bfloat16 th[32][33], tl[32][33];
    int bh = blockIdx.z;
    int n0 = blockIdx.x * 32, d0 = blockIdx.y * 32;
    int tx = threadIdx.x, ty = threadIdx.y;
#pragma unroll
    for (int j = 0; j < 32; j += 8) {
        size_t src = ((size_t)bh * 2048 + n0 + ty + j) * 64 + d0 + tx;
        th[ty + j][tx] = g_Vh[src];
        tl[ty + j][tx] = g_Vl[src];
    }
    __syncthreads();
#pragma unroll
    for (int j = 0; j < 32; j += 8) {
        size_t dst = ((size_t)bh * 64 + d0 + ty + j) * 2048 + n0 + tx;
        g_Vth[dst] = th[tx][ty + j];
        g_Vtl[dst] = tl[tx][ty + j];
    }
}

// ---------------------------------------------------------------------------
// HMMA bf16x3 GEMM with ldmatrix fragments + cp.async double buffering.
// C[4096,1024] = A @ B^T + bias (B stored [n][k]).
// Dynamic smem: 2 buffers x 4 tiles x 10240B = 80KB.
// Tile = 128 rows x 32 bf16, row stride TSTRIDE=20 words (80B).
// ---------------------------------------------------------------------------
#define TSTRIDE 20
#define GT 10240
#define GBUF (4 * GT)
#define GEMM_SMEM (2 * GBUF)

template <bool HEAD>
__device__ __forceinline__ void mma_gemm_body(const __nv_bfloat16* __restrict__ Ahi,
                                              const __nv_bfloat16* __restrict__ Alo,
                                              const __nv_bfloat16* __restrict__ Bhi,
                                              const __nv_bfloat16* __restrict__ Blo,
                                              const float* __restrict__ bias,
                                              float* __restrict__ out,
                                              __nv_bfloat16* __restrict__ outH,
                                              __nv_bfloat16* __restrict__ outL)
{
    extern __shared__ char gsm[];
    const uint32_t gb = smem_to_u32(gsm);

    const int tid = threadIdx.x;
    const int wid = tid >> 5;
    const int lid = tid & 31;
    const int wm  = wid & 3;
    const int wn  = wid >> 2;
    const int gq  = lid >> 2;
    const int tq  = lid & 3;
    const int lt  = lid >> 3;
    const int lr  = lid & 7;
    const int m0 = blockIdx.y * 128;
    const int n0 = blockIdx.x * 128;

    // cp.async loader geometry: thread -> 2 (row, c4) pairs
    const int u0row = (tid * 2) >> 2;
    const int u0c4  = (tid * 2) & 3;
    const int u1row = (tid * 2 + 1) >> 2;
    const int u1c4  = (tid * 2 + 1) & 3;

#define G_LOAD(kt, bi) do { \
        uint32_t buf = gb + (bi) * GBUF; \
        { \
            uint32_t so = (uint32_t)(u0row * TSTRIDE + u0c4 * 4) * 4; \
            const char* pa = (const char*)(Ahi + (size_t)(m0 + u0row) * 1024 + (kt)); \
            const char* pal = (const char*)(Alo + (size_t)(m0 + u0row) * 1024 + (kt)); \
            const char* pb = (const char*)(Bhi + (size_t)(n0 + u0row) * 1024 + (kt)); \
            const char* pbl = (const char*)(Blo + (size_t)(n0 + u0row) * 1024 + (kt)); \
            CP_ASYNC16(buf + so,          pa  + u0c4 * 16); \
            CP_ASYNC16(buf + GT + so,     pal + u0c4 * 16); \
            CP_ASYNC16(buf + 2 * GT + so, pb  + u0c4 * 16); \
            CP_ASYNC16(buf + 3 * GT + so, pbl + u0c4 * 16); \
        } \
        { \
            uint32_t so = (uint32_t)(u1row * TSTRIDE + u1c4 * 4) * 4; \
            const char* pa = (const char*)(Ahi + (size_t)(m0 + u1row) * 1024 + (kt)); \
            const char* pal = (const char*)(Alo + (size_t)(m0 + u1row) * 1024 + (kt)); \
            const char* pb = (const char*)(Bhi + (size_t)(n0 + u1row) * 1024 + (kt)); \
            const char* pbl = (const char*)(Blo + (size_t)(n0 + u1row) * 1024 + (kt)); \
            CP_ASYNC16(buf + so,          pa  + u1c4 * 16); \
            CP_ASYNC16(buf + GT + so,     pal + u1c4 * 16); \
            CP_ASYNC16(buf + 2 * GT + so, pb  + u1c4 * 16); \
            CP_ASYNC16(buf + 3 * GT + so, pbl + u1c4 * 16); \
        } \
        CP_COMMIT(); \
    } while (0)

    float acc[2][8][4];
#pragma unroll
    for (int mt = 0; mt < 2; mt++)
#pragma unroll
        for (int nt = 0; nt < 8; nt++)
#pragma unroll
            for (int e = 0; e < 4; e++) acc[mt][nt][e] = 0.f;

    G_LOAD(0, 0);
    G_LOAD(32, 1);

    for (int it = 0; it < 32; it++) {
        if (it == 31) { CP_WAIT0(); } else { CP_WAIT1(); }
        __syncthreads();

        const uint32_t buf = gb + (it & 1) * GBUF;
        const uint32_t uAh = buf;
        const uint32_t uAl = buf + GT;
        const uint32_t uBh = buf + 2 * GT;
        const uint32_t uBl = buf + 3 * GT;

#pragma unroll
        for (int ks = 0; ks < 2; ks++) {
            const int c0 = ks * 8;
            uint32_t bh[8][2], bl[8][2];
#pragma unroll
            for (int a = 0; a < 4; a++) {
                int row = wn * 64 + 16 * a + 8 * (lt >> 1) + lr;
                int col = c0 + 4 * (lt & 1);
                uint32_t off = (uint32_t)(row * TSTRIDE + col) * 4;
                uint32_t f[4];
                ldsm_x4(f, uBh + off);
                bh[2 * a][0] = f[0]; bh[2 * a][1] = f[1];
                bh[2 * a + 1][0] = f[2]; bh[2 * a + 1][1] = f[3];
                ldsm_x4(f, uBl + off);
                bl[2 * a][0] = f[0]; bl[2 * a][1] = f[1];
                bl[2 * a + 1][0] = f[2]; bl[2 * a + 1][1] = f[3];
            }
#pragma unroll
            for (int mt = 0; mt < 2; mt++) {
                int row = wm * 32 + 16 * mt + 8 * (lt & 1) + lr;
                int col = c0 + 4 * (lt >> 1);
                uint32_t off = (uint32_t)(row * TSTRIDE + col) * 4;
                uint32_t ah[4], al[4];
                ldsm_x4(ah, uAh + off);
                ldsm_x4(al, uAl + off);
#pragma unroll
                for (int nt = 0; nt < 8; nt++) {
                    mma_bf16(acc[mt][nt], ah, bh[nt]);
                    mma_bf16(acc[mt][nt], ah, bl[nt]);
                    mma_bf16(acc[mt][nt], al, bh[nt]);
                }
            }
        }
        __syncthreads();
        if (it + 2 < 32) G_LOAD((it + 2) * 32, it & 1);
    }

#pragma unroll
    for (int mt = 0; mt < 2; mt++) {
#pragma unroll
        for (int nt = 0; nt < 8; nt++) {
            int R = m0 + wm * 32 + mt * 16 + gq;
            int C = n0 + wn * 64 + nt * 8 + tq * 2;
            float b0 = bias[C], b1 = bias[C + 1];
#pragma unroll
            for (int half = 0; half < 2; half++) {
                int r = R + half * 8;
                float v0 = acc[mt][nt][half * 2 + 0] + b0;
                float v1 = acc[mt][nt][half * 2 + 1] + b1;
                if (HEAD) {
                    int b = r >> 11;
                    int n = r & 2047;
                    int hh = C >> 6;
                    int d = C & 63;
                    float h0, l0, h1, l1;
                    split1(v0, h0, l0);
                    split1(v1, h1, l1);
                    size_t ui = (((size_t)(b * Hn + hh)) * 2048 + n) * 32 + (d >> 1);
                    ((uint32_t*)outH)[ui] = pack2(h0, h1);
                    ((uint32_t*)outL)[ui] = pack2(l0, l1);
                } else {
                    *(float2*)(out + (size_t)r * 1024 + C) = make_float2(v0, v1);
                }
            }
        }
    }
#undef G_LOAD
}

__global__ void __launch_bounds__(256, 2)
mma_qkv(const float* __restrict__ bq, const float* __restrict__ bk,
        const float* __restrict__ bv)
{
    int z = blockIdx.z;
    const float* bias = (z == 0) ? bq : (z == 1) ? bk : bv;
    __nv_bfloat16* oh = (z == 0) ? g_Qh : (z == 1) ? g_Kh : g_Vh;
    __nv_bfloat16* ol = (z == 0) ? g_Ql : (z == 1) ? g_Kl : g_Vl;
    mma_gemm_body<true>(g_xh, g_xl, g_wth[z], g_wtl[z], bias, nullptr, oh, ol);
}

__global__ void __launch_bounds__(256, 2)
mma_out(const float* __restrict__ bo, float* __restrict__ out)
{
    mma_gemm_body<false>(g_oh, g_ol, g_wth[3], g_wtl[3], bo, out, nullptr, nullptr);
}

// ---------------------------------------------------------------------------
// HMMA flash attention v3: ldmatrix fragments + cp.async double buffering.
// BQ=128, BK=64, 8 warps. Dynamic smem 80KB:
//   [0,16K)   Q-lo (128x32 words, XOR swizzle)
//   [16K+bi*32K) buffers: Kh(8K) Kl(8K) Vh(8K) Vl(8K)
// ---------------------------------------------------------------------------
#define QSW(r, w) (((r) * 32) + ((w) ^ (((r) & 7) << 2)))
#define ATT_SMEM (16384 + 2 * 32768)

__global__ void __launch_bounds__(256, 2)
attn_mma(const float* __restrict__ Bg, const float* __restrict__ lam_p)
{
    extern __shared__ char smem[];
    const uint32_t sb = smem_to_u32(smem);

    const int tid = threadIdx.x;
    const int wm  = tid >> 5;
    const int lid = tid & 31;
    const int gq  = lid >> 2;
    const int tq  = lid & 3;
    const int lt  = lid >> 3;
    const int lr  = lid & 7;
    const int qb = blockIdx.x;
    const int h  = blockIdx.y;
    const int b  = blockIdx.z;
    const int bh = b * Hn + h;
    const int q0 = qb * 128;

    const float lam = __ldg(lam_p);
    const float scale = 0.125f;

    const int r0 = wm * 16 + gq;
    const int qrow = q0 + r0;

    const int ldrow = tid >> 2;
    const int ldq   = tid & 3;
    const uint32_t lw0 = (uint32_t)((4 * ldq) ^ ((ldrow & 7) << 2)) * 4;
    const uint32_t lw1 = (uint32_t)((4 * ldq + 16) ^ ((ldrow & 7) << 2)) * 4;
    const uint32_t lrow128 = (uint32_t)ldrow * 128;

#define LOAD_KB(kb, bi) do { \
        uint32_t bufb = sb + 16384 + (bi) * 32768; \
        const char* pKh = (const char*)(g_Kh + ((size_t)bh * 2048 + (kb) * 64 + ldrow) * 64); \
        const char* pKl = (const char*)(g_Kl + ((size_t)bh * 2048 + (kb) * 64 + ldrow) * 64); \
        const char* pVh = (const char*)(g_Vth + ((size_t)bh * 64 + ldrow) * 2048 + (kb) * 64); \
        const char* pVl = (const char*)(g_Vtl + ((size_t)bh * 64 + ldrow) * 2048 + (kb) * 64); \
        CP_ASYNC16(bufb + lrow128 + lw0, pKh + ldq * 16); \
        CP_ASYNC16(bufb + lrow128 + lw1, pKh + 64 + ldq * 16); \
        CP_ASYNC16(bufb + 8192 + lrow128 + lw0, pKl + ldq * 16); \
        CP_ASYNC16(bufb + 8192 + lrow128 + lw1, pKl + 64 + ldq * 16); \
        CP_ASYNC16(bufb + 16384 + lrow128 + lw0, pVh + ldq * 16); \
        CP_ASYNC16(bufb + 16384 + lrow128 + lw1, pVh + 64 + ldq * 16); \
        CP_ASYNC16(bufb + 24576 + lrow128 + lw0, pVl + ldq * 16); \
        CP_ASYNC16(bufb + 24576 + lrow128 + lw1, pVl + 64 + ldq * 16); \
        CP_COMMIT(); \
    } while (0)

    // Q-lo tile -> smem
    {
        const __nv_bfloat16* Qlg = g_Ql + ((size_t)bh * 2048 + q0) * 64;
#pragma unroll
        for (int i = 0; i < 4; i++) {
            int u = tid + i * 256;
            int row = u >> 3;
            int c4 = u & 7;
            int w = (4 * c4) ^ ((row & 7) << 2);
            *(uint4*)(smem + (row * 32 + w) * 4) = ((const uint4*)(Qlg + (size_t)row * 64))[c4];
        }
    }

    // Q-hi fragments -> registers
    uint32_t qh[4][4];
    {
        const uint32_t* Q32 = (const uint32_t*)g_Qh;
        size_t base0 = ((size_t)bh * 2048 + qrow) * 32;
        size_t base1 = base0 + 8 * 32;
#pragma unroll
        for (int kt = 0; kt < 4; kt++) {
            qh[kt][0] = Q32[base0 + 8 * kt + tq];
            qh[kt][1] = Q32[base1 + 8 * kt + tq];
            qh[kt][2] = Q32[base0 + 8 * kt + 4 + tq];
            qh[kt][3] = Q32[base1 + 8 * kt + 4 + tq];
        }
    }

    LOAD_KB(0, 0);
    LOAD_KB(1, 1);

    float m_i[2] = {-1e30f, -1e30f};
    float l_i[2] = {0.f, 0.f};
    float o[8][4];
#pragma unroll
    for (int nt = 0; nt < 8; nt++)
#pragma unroll
        for (int e = 0; e < 4; e++) o[nt][e] = 0.f;

    const float* Bgb = Bg + (size_t)b * Nseq * Nseq;

    for (int kb = 0; kb < 32; kb++) {
        if (kb == 31) { CP_WAIT0(); } else { CP_WAIT1(); }
        __syncthreads();

        const uint32_t bufb = sb + 16384 + (kb & 1) * 32768;
        const uint32_t uKh = bufb;
        const uint32_t uKl = bufb + 8192;
        const uint32_t uVh = bufb + 16384;
        const uint32_t uVl = bufb + 24576;

        float s[8][4];
#pragma unroll
        for (int nt = 0; nt < 8; nt++)
#pragma unroll
            for (int e = 0; e < 4; e++) s[nt][e] = 0.f;

#pragma unroll
        for (int kt = 0; kt < 4; kt++) {
            uint32_t al[4];
            {
                int row = wm * 16 + 8 * (lt & 1) + lr;
                int wb = 8 * kt + 4 * (lt >> 1);
                ldsm_x4(al, sb + (uint32_t)QSW(row, wb) * 4);
            }
#pragma unroll
            for (int a = 0; a < 4; a++) {
                int row = 16 * a + 8 * (lt >> 1) + lr;
                int wb = 8 * kt + 4 * (lt & 1);
                uint32_t off = (uint32_t)QSW(row, wb) * 4;
                uint32_t kh4[4], kl4[4];
                ldsm_x4(kh4, uKh + off);
                ldsm_x4(kl4, uKl + off);
                uint32_t kh0[2] = {kh4[0], kh4[1]}, kh1[2] = {kh4[2], kh4[3]};
                uint32_t kl0[2] = {kl4[0], kl4[1]}, kl1[2] = {kl4[2], kl4[3]};
                mma_bf16(s[2 * a], qh[kt], kh0);
                mma_bf16(s[2 * a], qh[kt], kl0);
                mma_bf16(s[2 * a], al, kh0);
                mma_bf16(s[2 * a + 1], qh[kt], kh1);
                mma_bf16(s[2 * a + 1], qh[kt], kl1);
                mma_bf16(s[2 * a + 1], al, kh1);
            }
        }

#pragma unroll
        for (int nt = 0; nt < 8; nt++) {
#pragma unroll
            for (int half = 0; half < 2; half++) {
                int row = qrow + half * 8;
                float2 bg = *(const float2*)(Bgb + (size_t)row * 2048 +
                                             kb * 64 + nt * 8 + tq * 2);
                s[nt][half * 2 + 0] = s[nt][half * 2 + 0] * scale + lam * bg.x;
                s[nt][half * 2 + 1] = s[nt][half * 2 + 1] * scale + lam * bg.y;
            }
        }

#pragma unroll
        for (int half = 0; half < 2; half++) {
            float mx = -1e30f;
#pragma unroll
            for (int nt = 0; nt < 8; nt++)
                mx = fmaxf(mx, fmaxf(s[nt][half * 2], s[nt][half * 2 + 1]));
            mx = fmaxf(mx, __shfl_xor_sync(0xffffffffu, mx, 1));
            mx = fmaxf(mx, __shfl_xor_sync(0xffffffffu, mx, 2));
            float mn = fmaxf(m_i[half], mx);
            float corr = __expf(m_i[half] - mn);
            m_i[half] = mn;
            float rs = 0.f;
#pragma unroll
            for (int nt = 0; nt < 8; nt++) {
                s[nt][half * 2]     = __expf(s[nt][half * 2] - mn);
                s[nt][half * 2 + 1] = __expf(s[nt][half * 2 + 1] - mn);
                rs += s[nt][half * 2] + s[nt][half * 2 + 1];
            }
            rs += __shfl_xor_sync(0xffffffffu, rs, 1);
            rs += __shfl_xor_sync(0xffffffffu, rs, 2);
            l_i[half] = l_i[half] * corr + rs;
#pragma unroll
            for (int nt = 0; nt < 8; nt++) {
                o[nt][half * 2]     *= corr;
                o[nt][half * 2 + 1] *= corr;
            }
        }

#pragma unroll
        for (int kt = 0; kt < 4; kt++) {
            float h0, l0, h1, l1, h2, l2, h3, l3;
            uint32_t ph[4], pl[4];
            split1(s[2 * kt][0], h0, l0); split1(s[2 * kt][1], h1, l1);
            split1(s[2 * kt][2], h2, l2); split1(s[2 * kt][3], h3, l3);
            ph[0] = pack2(h0, h1); pl[0] = pack2(l0, l1);
            ph[1] = pack2(h2, h3); pl[1] = pack2(l2, l3);
            split1(s[2 * kt + 1][0], h0, l0); split1(s[2 * kt + 1][1], h1, l1);
            split1(s[2 * kt + 1][2], h2, l2); split1(s[2 * kt + 1][3], h3, l3);
            ph[2] = pack2(h0, h1); pl[2] = pack2(l0, l1);
            ph[3] = pack2(h2, h3); pl[3] = pack2(l2, l3);
#pragma unroll
            for (int a = 0; a < 4; a++) {
                int row = 16 * a + 8 * (lt >> 1) + lr;
                int wb = 8 * kt + 4 * (lt & 1);
                uint32_t off = (uint32_t)QSW(row, wb) * 4;
                uint32_t vh4[4], vl4[4];
                ldsm_x4(vh4, uVh + off);
                ldsm_x4(vl4, uVl + off);
                uint32_t vh0[2] = {vh4[0], vh4[1]}, vh1[2] = {vh4[2], vh4[3]};
                uint32_t vl0[2] = {vl4[0], vl4[1]}, vl1[2] = {vl4[2], vl4[3]};
                mma_bf16(o[2 * a], ph, vh0);
                mma_bf16(o[2 * a], ph, vl0);
                mma_bf16(o[2 * a], pl, vh0);
                mma_bf16(o[2 * a + 1], ph, vh1);
                mma_bf16(o[2 * a + 1], ph, vl1);
                mma_bf16(o[2 * a + 1], pl, vh1);
            }
        }

        __syncthreads();
        if (kb + 2 < 32) LOAD_KB(kb + 2, kb & 1);
    }

    float inv0 = 1.0f / l_i[0];
    float inv1 = 1.0f / l_i[1];
#pragma unroll
    for (int nt = 0; nt < 8; nt++) {
#pragma unroll
        for (int half = 0; half < 2; half++) {
            float inv = half ? inv1 : inv0;
            int row = qrow + half * 8;
            float v0 = o[nt][half * 2 + 0] * inv;
            float v1 = o[nt][half * 2 + 1] * inv;
            float h0, l0, h1, l1;
            split1(v0, h0, l0);
            split1(v1, h1, l1);
            size_t ui = ((size_t)(b * 2048) + row) * 512 + h * 32 + nt * 4 + tq;
            ((uint32_t*)g_oh)[ui] = pack2(h0, h1);
            ((uint32_t*)g_ol)[ui] = pack2(l0, l1);
        }
    }
}

// ---------------------------------------------------------------------------
extern "C" void kernel_launch(void* const* d_in, const int* in_sizes, int n_in,
                              void* d_out, int out_size)
{
    const float* x   = (const float*)d_in[0];
    const float* Bg  = (const float*)d_in[1];
    const float* Wq  = (const float*)d_in[2];
    const float* bq  = (const float*)d_in[3];
    const float* Wk  = (const float*)d_in[4];
    const float* bk  = (const float*)d_in[5];
    const float* Wv  = (const float*)d_in[6];
    const float* bv  = (const float*)d_in[7];
    const float* Wo  = (const float*)d_in[8];
    const float* bo  = (const float*)d_in[9];
    const float* lam = (const float*)d_in[10];
    float* out = (float*)d_out;

    cudaFuncSetAttribute(attn_mma, cudaFuncAttributeMaxDynamicSharedMemorySize, ATT_SMEM);
    cudaFuncSetAttribute(mma_qkv, cudaFuncAttributeMaxDynamicSharedMemorySize, GEMM_SMEM);
    cudaFuncSetAttribute(mma_out, cudaFuncAttributeMaxDynamicSharedMemorySize, GEMM_SMEM);

    conv_split_x<<<4096, 256>>>((const float4*)x);
    conv_w<<<dim3(32, 32, 4), dim3(32, 8)>>>(Wq, Wk, Wv, Wo);

    mma_qkv<<<dim3(8, 32, 3), 256, GEMM_SMEM>>>(bq, bk, bv);
    transpose_v<<<dim3(64, 2, 32), dim3(32, 8)>>>();

    attn_mma<<<dim3(16, 16, 2), 256, ATT_SMEM>>>(Bg, lam);

    mma_out<<<dim3(8, 32, 1), 256, GEMM_SMEM>>>(bo, out);
}